// round 1
// baseline (speedup 1.0000x reference)
#include <cuda_runtime.h>

#define SEQ   16384
#define DIM   1280
#define NH    16
#define HD    80
#define WIN   64
#define NWIN  (SEQ / WIN)
#define HDP   84   // padded head-dim row in smem (conflict-free LDS.128)
#define SCP   65   // padded score row stride

// Scratch (no allocations allowed in kernel_launch; __device__ globals are the sanctioned path)
__device__ float g_q[SEQ * DIM];
__device__ float g_k[SEQ * DIM];
__device__ float g_v[SEQ * DIM];
__device__ float g_o[SEQ * DIM];

// ---------------------------------------------------------------------------
// C[M,N] = A[M,K] @ W[N,K]^T + bias   (M=SEQ, N=K=DIM)
// 128x128 block tile, BK=8, 256 threads, 8x8 per-thread microtile.
// a_sel: 0 -> A_ext, 1 -> g_o.   c_sel: 0 -> C_ext, 1 -> g_q, 2 -> g_k, 3 -> g_v
// ---------------------------------------------------------------------------
__global__ __launch_bounds__(256, 2)
void gemm_nt(const float* __restrict__ A_ext, int a_sel,
             const float* __restrict__ W, const float* __restrict__ bias,
             float* C_ext, int c_sel)
{
    const float* A = a_sel ? g_o : A_ext;
    float* C = (c_sel == 0) ? C_ext
             : (c_sel == 1) ? g_q
             : (c_sel == 2) ? g_k : g_v;

    __shared__ float As[8][128];
    __shared__ float Bs[8][128];

    const int tid = threadIdx.x;
    const int bm = blockIdx.y * 128;
    const int bn = blockIdx.x * 128;

    const int lr = tid >> 1;          // 0..127 (tile row to load)
    const int lc = (tid & 1) * 4;     // 0 or 4 (k sub-offset)

    const float* Ap = A + (size_t)(bm + lr) * DIM + lc;
    const float* Wq = W + (size_t)(bn + lr) * DIM + lc;

    const int tm = (tid >> 4) * 8;    // microtile row
    const int tn = (tid & 15) * 8;    // microtile col

    float acc[8][8];
#pragma unroll
    for (int i = 0; i < 8; i++)
#pragma unroll
        for (int j = 0; j < 8; j++) acc[i][j] = 0.f;

    for (int k0 = 0; k0 < DIM; k0 += 8) {
        float4 av = *(const float4*)(Ap + k0);
        float4 wv = *(const float4*)(Wq + k0);
        As[lc + 0][lr] = av.x; As[lc + 1][lr] = av.y;
        As[lc + 2][lr] = av.z; As[lc + 3][lr] = av.w;
        Bs[lc + 0][lr] = wv.x; Bs[lc + 1][lr] = wv.y;
        Bs[lc + 2][lr] = wv.z; Bs[lc + 3][lr] = wv.w;
        __syncthreads();
#pragma unroll
        for (int k = 0; k < 8; k++) {
            float a[8], b[8];
            *(float4*)(a)     = *(const float4*)&As[k][tm];
            *(float4*)(a + 4) = *(const float4*)&As[k][tm + 4];
            *(float4*)(b)     = *(const float4*)&Bs[k][tn];
            *(float4*)(b + 4) = *(const float4*)&Bs[k][tn + 4];
#pragma unroll
            for (int i = 0; i < 8; i++)
#pragma unroll
                for (int j = 0; j < 8; j++)
                    acc[i][j] += a[i] * b[j];
        }
        __syncthreads();
    }

    float bv[8];
#pragma unroll
    for (int j = 0; j < 8; j++) bv[j] = bias[bn + tn + j];

#pragma unroll
    for (int i = 0; i < 8; i++) {
        float4 v0, v1;
        v0.x = acc[i][0] + bv[0]; v0.y = acc[i][1] + bv[1];
        v0.z = acc[i][2] + bv[2]; v0.w = acc[i][3] + bv[3];
        v1.x = acc[i][4] + bv[4]; v1.y = acc[i][5] + bv[5];
        v1.z = acc[i][6] + bv[6]; v1.w = acc[i][7] + bv[7];
        float* cp = C + (size_t)(bm + tm + i) * DIM + bn + tn;
        *(float4*)(cp)     = v0;
        *(float4*)(cp + 4) = v1;
    }
}

// ---------------------------------------------------------------------------
// In-place RoPE on g_q and g_k.
// out = x*cos + rotate_half(x)*sin ; rotate_half pairs (d, d+40).
// ---------------------------------------------------------------------------
__global__ void rope_kernel(const float* __restrict__ cosp,
                            const float* __restrict__ sinp)
{
    const int total = SEQ * NH * (HD / 2);
    int idx = blockIdx.x * blockDim.x + threadIdx.x;
    if (idx >= total) return;
    int d = idx % (HD / 2);
    int h = (idx / (HD / 2)) % NH;
    int s = idx / ((HD / 2) * NH);

    float c1 = cosp[s * HD + d];
    float s1 = sinp[s * HD + d];
    float c2 = cosp[s * HD + d + HD / 2];
    float s2 = sinp[s * HD + d + HD / 2];

    size_t o1 = (size_t)s * DIM + h * HD + d;
    size_t o2 = o1 + HD / 2;

    float q1 = g_q[o1], q2 = g_q[o2];
    g_q[o1] = q1 * c1 - q2 * s1;       // d < 40: x*cos - x[d+40]*sin
    g_q[o2] = q2 * c2 + q1 * s2;       // d >= 40: x*cos + x[d-40]*sin

    float k1 = g_k[o1], k2 = g_k[o2];
    g_k[o1] = k1 * c1 - k2 * s1;
    g_k[o2] = k2 * c2 + k1 * s2;
}

// ---------------------------------------------------------------------------
// Windowed attention: one block per (window, head). 64x64 scores, D=80.
// ---------------------------------------------------------------------------
__global__ __launch_bounds__(256)
void attn_win()
{
    extern __shared__ float sm[];
    float* qs = sm;                    // [64][84]
    float* ks = qs + WIN * HDP;        // [64][84]
    float* vs = ks + WIN * HDP;        // [64][84]
    float* sc = vs + WIN * HDP;        // [64][65]

    const int w = blockIdx.x;
    const int h = blockIdx.y;
    const int tid = threadIdx.x;
    const size_t base = (size_t)(w * WIN) * DIM + (size_t)h * HD;

    // stage q/k/v tiles (coalesced float4)
    for (int idx = tid; idx < WIN * (HD / 4); idx += 256) {
        int row = idx / (HD / 4);
        int col = (idx % (HD / 4)) * 4;
        size_t g = base + (size_t)row * DIM + col;
        *(float4*)(qs + row * HDP + col) = *(const float4*)(g_q + g);
        *(float4*)(ks + row * HDP + col) = *(const float4*)(g_k + g);
        *(float4*)(vs + row * HDP + col) = *(const float4*)(g_v + g);
    }
    __syncthreads();

    // scores: thread (i = tid&63, j-block = (tid>>6)*16)
    const float scale = 0.11180339887498949f;  // 1/sqrt(80)
    {
        const int i  = tid & 63;
        const int jb = (tid >> 6) * 16;
        for (int j = jb; j < jb + 16; j++) {
            float s = 0.f;
#pragma unroll
            for (int d = 0; d < HD; d += 4) {
                float4 qv = *(const float4*)(qs + i * HDP + d);
                float4 kv = *(const float4*)(ks + j * HDP + d);
                s += qv.x * kv.x + qv.y * kv.y + qv.z * kv.z + qv.w * kv.w;
            }
            sc[i * SCP + j] = s * scale;
        }
    }
    __syncthreads();

    // row softmax: one thread per row
    if (tid < WIN) {
        float m = -1e30f;
        for (int j = 0; j < WIN; j++) m = fmaxf(m, sc[tid * SCP + j]);
        float sum = 0.f;
        for (int j = 0; j < WIN; j++) {
            float e = __expf(sc[tid * SCP + j] - m);
            sc[tid * SCP + j] = e;
            sum += e;
        }
        float inv = 1.f / sum;
        for (int j = 0; j < WIN; j++) sc[tid * SCP + j] *= inv;
    }
    __syncthreads();

    // out = P @ V
    for (int idx = tid; idx < WIN * HD; idx += 256) {
        int i = idx / HD;
        int d = idx % HD;
        float s = 0.f;
#pragma unroll 8
        for (int j = 0; j < WIN; j++)
            s += sc[i * SCP + j] * vs[j * HDP + d];
        g_o[base + (size_t)i * DIM + d] = s;
    }
}

// ---------------------------------------------------------------------------
extern "C" void kernel_launch(void* const* d_in, const int* in_sizes, int n_in,
                              void* d_out, int out_size)
{
    const float* hs   = (const float*)d_in[0];
    const float* cosp = (const float*)d_in[1];
    const float* sinp = (const float*)d_in[2];
    const float* Wq   = (const float*)d_in[3];
    const float* bq   = (const float*)d_in[4];
    const float* Wk   = (const float*)d_in[5];
    const float* bk   = (const float*)d_in[6];
    const float* Wv   = (const float*)d_in[7];
    const float* bv   = (const float*)d_in[8];
    const float* Wp   = (const float*)d_in[9];
    const float* bp   = (const float*)d_in[10];
    float* out = (float*)d_out;

    dim3 gg(DIM / 128, SEQ / 128);

    gemm_nt<<<gg, 256>>>(hs, 0, Wq, bq, nullptr, 1);   // -> g_q
    gemm_nt<<<gg, 256>>>(hs, 0, Wk, bk, nullptr, 2);   // -> g_k
    gemm_nt<<<gg, 256>>>(hs, 0, Wv, bv, nullptr, 3);   // -> g_v

    const int nrope = SEQ * NH * (HD / 2);
    rope_kernel<<<(nrope + 255) / 256, 256>>>(cosp, sinp);

    const int smem = (3 * WIN * HDP + WIN * SCP) * (int)sizeof(float);  // 81152 B
    cudaFuncSetAttribute(attn_win, cudaFuncAttributeMaxDynamicSharedMemorySize, smem);
    attn_win<<<dim3(NWIN, NH), 256, smem>>>();

    gemm_nt<<<gg, 256>>>(nullptr, 1, Wp, bp, out, 0);  // -> d_out
}

// round 2
// speedup vs baseline: 1.9801x; 1.9801x over previous
#include <cuda_runtime.h>
#include <cuda_bf16.h>
#include <mma.h>

using namespace nvcuda;

#define SEQ   16384
#define DIM   1280
#define NH    16
#define HD    80
#define WIN   64
#define NWIN  (SEQ / WIN)
#define HDP   84   // padded head-dim row in smem
#define SCP   65   // padded score row stride

// GEMM tiling
#define GBM   128
#define GBN   128
#define GBK   32
#define GLDS  40   // padded smem stride (80B rows -> conflict-free 16B fetches)

// ---------------------------------------------------------------------------
// Scratch (__device__ globals; no allocations allowed)
// ---------------------------------------------------------------------------
__device__ float g_q[SEQ * DIM];
__device__ float g_k[SEQ * DIM];
__device__ float g_v[SEQ * DIM];
__device__ __nv_bfloat16 g_ahi[SEQ * DIM];   // A-operand hi split (hs, then attn out)
__device__ __nv_bfloat16 g_alo[SEQ * DIM];   // A-operand lo split
__device__ __nv_bfloat16 g_whi[DIM * DIM];   // W hi split
__device__ __nv_bfloat16 g_wlo[DIM * DIM];   // W lo split

// ---------------------------------------------------------------------------
// fp32 -> bf16 (hi) + bf16 (residual lo), vectorized by 4
// ---------------------------------------------------------------------------
__global__ void split_kernel(const float* __restrict__ src,
                             __nv_bfloat16* __restrict__ hi,
                             __nv_bfloat16* __restrict__ lo, int n4)
{
    int i = blockIdx.x * blockDim.x + threadIdx.x;
    if (i >= n4) return;
    float4 v = ((const float4*)src)[i];
    __nv_bfloat16 h0 = __float2bfloat16(v.x);
    __nv_bfloat16 h1 = __float2bfloat16(v.y);
    __nv_bfloat16 h2 = __float2bfloat16(v.z);
    __nv_bfloat16 h3 = __float2bfloat16(v.w);
    __nv_bfloat16 l0 = __float2bfloat16(v.x - __bfloat162float(h0));
    __nv_bfloat16 l1 = __float2bfloat16(v.y - __bfloat162float(h1));
    __nv_bfloat16 l2 = __float2bfloat16(v.z - __bfloat162float(h2));
    __nv_bfloat16 l3 = __float2bfloat16(v.w - __bfloat162float(h3));
    __nv_bfloat162* hp = (__nv_bfloat162*)hi;
    __nv_bfloat162* lp = (__nv_bfloat162*)lo;
    hp[2 * i]     = __nv_bfloat162(h0, h1);
    hp[2 * i + 1] = __nv_bfloat162(h2, h3);
    lp[2 * i]     = __nv_bfloat162(l0, l1);
    lp[2 * i + 1] = __nv_bfloat162(l2, l3);
}

// ---------------------------------------------------------------------------
// C[M,N] = (Ah+Al)[M,K] @ (Wh+Wl)[N,K]^T  via bf16x3 (drop Al*Wl term).
// 128x128 tile, BK=32, 256 threads (8 warps, 2x4), warp tile 64x32.
// No bias (folded into consumers).
// ---------------------------------------------------------------------------
__global__ __launch_bounds__(256, 1)
void gemm_bf16x3(const __nv_bfloat16* __restrict__ Ah,
                 const __nv_bfloat16* __restrict__ Al,
                 const __nv_bfloat16* __restrict__ Bh,
                 const __nv_bfloat16* __restrict__ Bl,
                 float* __restrict__ C)
{
    __shared__ __nv_bfloat16 sAh[GBM * GLDS];
    __shared__ __nv_bfloat16 sAl[GBM * GLDS];
    __shared__ __nv_bfloat16 sBh[GBN * GLDS];
    __shared__ __nv_bfloat16 sBl[GBN * GLDS];

    const int tid = threadIdx.x;
    const int bm = blockIdx.y * GBM;
    const int bn = blockIdx.x * GBN;

    const int warp = tid >> 5;
    const int wm = (warp & 1) * 64;    // warp row offset within tile
    const int wn = (warp >> 1) * 32;   // warp col offset within tile

    wmma::fragment<wmma::accumulator, 16, 16, 16, float> acc[4][2];
#pragma unroll
    for (int i = 0; i < 4; i++)
#pragma unroll
        for (int j = 0; j < 2; j++) wmma::fill_fragment(acc[i][j], 0.0f);

    // loader: 8-elem (16B) chunks; rows r0 and r0+64, col chunk c0
    const int r0 = tid >> 2;
    const int c0 = (tid & 3) * 8;

    uint4 rAh0, rAh1, rAl0, rAl1, rBh0, rBh1, rBl0, rBl1;

    auto ldg = [&](int k0) {
        const size_t a0 = (size_t)(bm + r0) * DIM + k0 + c0;
        const size_t a1 = (size_t)(bm + r0 + 64) * DIM + k0 + c0;
        const size_t b0 = (size_t)(bn + r0) * DIM + k0 + c0;
        const size_t b1 = (size_t)(bn + r0 + 64) * DIM + k0 + c0;
        rAh0 = *(const uint4*)(Ah + a0);  rAh1 = *(const uint4*)(Ah + a1);
        rAl0 = *(const uint4*)(Al + a0);  rAl1 = *(const uint4*)(Al + a1);
        rBh0 = *(const uint4*)(Bh + b0);  rBh1 = *(const uint4*)(Bh + b1);
        rBl0 = *(const uint4*)(Bl + b0);  rBl1 = *(const uint4*)(Bl + b1);
    };

    auto sts = [&]() {
        const int s0 = r0 * GLDS + c0;
        const int s1 = (r0 + 64) * GLDS + c0;
        *(uint2*)&sAh[s0]     = make_uint2(rAh0.x, rAh0.y);
        *(uint2*)&sAh[s0 + 4] = make_uint2(rAh0.z, rAh0.w);
        *(uint2*)&sAh[s1]     = make_uint2(rAh1.x, rAh1.y);
        *(uint2*)&sAh[s1 + 4] = make_uint2(rAh1.z, rAh1.w);
        *(uint2*)&sAl[s0]     = make_uint2(rAl0.x, rAl0.y);
        *(uint2*)&sAl[s0 + 4] = make_uint2(rAl0.z, rAl0.w);
        *(uint2*)&sAl[s1]     = make_uint2(rAl1.x, rAl1.y);
        *(uint2*)&sAl[s1 + 4] = make_uint2(rAl1.z, rAl1.w);
        *(uint2*)&sBh[s0]     = make_uint2(rBh0.x, rBh0.y);
        *(uint2*)&sBh[s0 + 4] = make_uint2(rBh0.z, rBh0.w);
        *(uint2*)&sBh[s1]     = make_uint2(rBh1.x, rBh1.y);
        *(uint2*)&sBh[s1 + 4] = make_uint2(rBh1.z, rBh1.w);
        *(uint2*)&sBl[s0]     = make_uint2(rBl0.x, rBl0.y);
        *(uint2*)&sBl[s0 + 4] = make_uint2(rBl0.z, rBl0.w);
        *(uint2*)&sBl[s1]     = make_uint2(rBl1.x, rBl1.y);
        *(uint2*)&sBl[s1 + 4] = make_uint2(rBl1.z, rBl1.w);
    };

    ldg(0);

    for (int k0 = 0; k0 < DIM; k0 += GBK) {
        sts();
        __syncthreads();
        if (k0 + GBK < DIM) ldg(k0 + GBK);

#pragma unroll
        for (int kk = 0; kk < GBK; kk += 16) {
            wmma::fragment<wmma::matrix_a, 16, 16, 16, __nv_bfloat16, wmma::row_major> fah[4], fal[4];
            wmma::fragment<wmma::matrix_b, 16, 16, 16, __nv_bfloat16, wmma::col_major> fbh[2], fbl[2];
#pragma unroll
            for (int i = 0; i < 4; i++) {
                wmma::load_matrix_sync(fah[i], &sAh[(wm + i * 16) * GLDS + kk], GLDS);
                wmma::load_matrix_sync(fal[i], &sAl[(wm + i * 16) * GLDS + kk], GLDS);
            }
#pragma unroll
            for (int j = 0; j < 2; j++) {
                wmma::load_matrix_sync(fbh[j], &sBh[(wn + j * 16) * GLDS + kk], GLDS);
                wmma::load_matrix_sync(fbl[j], &sBl[(wn + j * 16) * GLDS + kk], GLDS);
            }
#pragma unroll
            for (int i = 0; i < 4; i++)
#pragma unroll
                for (int j = 0; j < 2; j++) {
                    wmma::mma_sync(acc[i][j], fah[i], fbh[j], acc[i][j]);
                    wmma::mma_sync(acc[i][j], fah[i], fbl[j], acc[i][j]);
                    wmma::mma_sync(acc[i][j], fal[i], fbh[j], acc[i][j]);
                }
        }
        __syncthreads();
    }

#pragma unroll
    for (int i = 0; i < 4; i++)
#pragma unroll
        for (int j = 0; j < 2; j++)
            wmma::store_matrix_sync(&C[(size_t)(bm + wm + i * 16) * DIM + bn + wn + j * 16],
                                    acc[i][j], DIM, wmma::mem_row_major);
}

// ---------------------------------------------------------------------------
// Windowed attention with fused bias + RoPE on load; writes bf16 hi/lo split.
// One block per (window, head).
// ---------------------------------------------------------------------------
__global__ __launch_bounds__(256)
void attn_win(const float* __restrict__ cosp, const float* __restrict__ sinp,
              const float* __restrict__ bq, const float* __restrict__ bk,
              const float* __restrict__ bv)
{
    extern __shared__ float sm[];
    float* qs = sm;                    // [64][84]
    float* ks = qs + WIN * HDP;        // [64][84]
    float* vs = ks + WIN * HDP;        // [64][84]
    float* sc = vs + WIN * HDP;        // [64][65]

    const int w = blockIdx.x;
    const int h = blockIdx.y;
    const int tid = threadIdx.x;
    const size_t base = (size_t)(w * WIN) * DIM + (size_t)h * HD;

    // stage q/k with fused bias + rope (pairs d, d+40)
    for (int idx = tid; idx < WIN * (HD / 2); idx += 256) {
        int row = idx / (HD / 2);
        int d   = idx % (HD / 2);
        int s   = w * WIN + row;
        float c1 = cosp[s * HD + d],          s1 = sinp[s * HD + d];
        float c2 = cosp[s * HD + d + HD / 2], s2 = sinp[s * HD + d + HD / 2];
        size_t o1 = base + (size_t)row * DIM + d;
        size_t o2 = o1 + HD / 2;

        float q1 = g_q[o1] + bq[h * HD + d];
        float q2 = g_q[o2] + bq[h * HD + d + HD / 2];
        qs[row * HDP + d]          = q1 * c1 - q2 * s1;
        qs[row * HDP + d + HD / 2] = q2 * c2 + q1 * s2;

        float k1 = g_k[o1] + bk[h * HD + d];
        float k2 = g_k[o2] + bk[h * HD + d + HD / 2];
        ks[row * HDP + d]          = k1 * c1 - k2 * s1;
        ks[row * HDP + d + HD / 2] = k2 * c2 + k1 * s2;
    }
    // stage v with fused bias
    for (int idx = tid; idx < WIN * (HD / 4); idx += 256) {
        int row = idx / (HD / 4);
        int col = (idx % (HD / 4)) * 4;
        size_t g = base + (size_t)row * DIM + col;
        float4 vv = *(const float4*)(g_v + g);
        vv.x += bv[h * HD + col + 0];
        vv.y += bv[h * HD + col + 1];
        vv.z += bv[h * HD + col + 2];
        vv.w += bv[h * HD + col + 3];
        *(float4*)(vs + row * HDP + col) = vv;
    }
    __syncthreads();

    // scores
    const float scale = 0.11180339887498949f;  // 1/sqrt(80)
    {
        const int i  = tid & 63;
        const int jb = (tid >> 6) * 16;
        for (int j = jb; j < jb + 16; j++) {
            float s = 0.f;
#pragma unroll
            for (int d = 0; d < HD; d += 4) {
                float4 qv = *(const float4*)(qs + i * HDP + d);
                float4 kv = *(const float4*)(ks + j * HDP + d);
                s += qv.x * kv.x + qv.y * kv.y + qv.z * kv.z + qv.w * kv.w;
            }
            sc[i * SCP + j] = s * scale;
        }
    }
    __syncthreads();

    // row softmax
    if (tid < WIN) {
        float m = -1e30f;
        for (int j = 0; j < WIN; j++) m = fmaxf(m, sc[tid * SCP + j]);
        float sum = 0.f;
        for (int j = 0; j < WIN; j++) {
            float e = __expf(sc[tid * SCP + j] - m);
            sc[tid * SCP + j] = e;
            sum += e;
        }
        float inv = 1.f / sum;
        for (int j = 0; j < WIN; j++) sc[tid * SCP + j] *= inv;
    }
    __syncthreads();

    // out = P @ V, written as bf16 hi/lo split (A-operand of final GEMM)
    for (int idx = tid; idx < WIN * HD; idx += 256) {
        int i = idx / HD;
        int d = idx % HD;
        float s = 0.f;
#pragma unroll 8
        for (int j = 0; j < WIN; j++)
            s += sc[i * SCP + j] * vs[j * HDP + d];
        size_t o = base + (size_t)i * DIM + d;
        __nv_bfloat16 hi = __float2bfloat16(s);
        g_ahi[o] = hi;
        g_alo[o] = __float2bfloat16(s - __bfloat162float(hi));
    }
}

// ---------------------------------------------------------------------------
// out[s, :] += bp  (vectorized)
// ---------------------------------------------------------------------------
__global__ void bias_add(float* __restrict__ out, const float* __restrict__ bp)
{
    int i = blockIdx.x * blockDim.x + threadIdx.x;   // over SEQ*DIM/4
    float4 v = ((float4*)out)[i];
    int col = (i * 4) % DIM;
    v.x += bp[col + 0];
    v.y += bp[col + 1];
    v.z += bp[col + 2];
    v.w += bp[col + 3];
    ((float4*)out)[i] = v;
}

// ---------------------------------------------------------------------------
extern "C" void kernel_launch(void* const* d_in, const int* in_sizes, int n_in,
                              void* d_out, int out_size)
{
    const float* hs   = (const float*)d_in[0];
    const float* cosp = (const float*)d_in[1];
    const float* sinp = (const float*)d_in[2];
    const float* Wq   = (const float*)d_in[3];
    const float* bq   = (const float*)d_in[4];
    const float* Wk   = (const float*)d_in[5];
    const float* bk   = (const float*)d_in[6];
    const float* Wv   = (const float*)d_in[7];
    const float* bv   = (const float*)d_in[8];
    const float* Wp   = (const float*)d_in[9];
    const float* bp   = (const float*)d_in[10];
    float* out = (float*)d_out;

    float *pq, *pk, *pv;
    __nv_bfloat16 *pah, *pal, *pwh, *pwl;
    cudaGetSymbolAddress((void**)&pq,  g_q);
    cudaGetSymbolAddress((void**)&pk,  g_k);
    cudaGetSymbolAddress((void**)&pv,  g_v);
    cudaGetSymbolAddress((void**)&pah, g_ahi);
    cudaGetSymbolAddress((void**)&pal, g_alo);
    cudaGetSymbolAddress((void**)&pwh, g_whi);
    cudaGetSymbolAddress((void**)&pwl, g_wlo);

    const int nA4 = SEQ * DIM / 4;     // 5,242,880
    const int nW4 = DIM * DIM / 4;     // 409,600
    dim3 gg(DIM / GBN, SEQ / GBM);     // (10, 128)

    // split activations once
    split_kernel<<<(nA4 + 255) / 256, 256>>>(hs, pah, pal, nA4);

    // Q
    split_kernel<<<(nW4 + 255) / 256, 256>>>(Wq, pwh, pwl, nW4);
    gemm_bf16x3<<<gg, 256>>>(pah, pal, pwh, pwl, pq);
    // K
    split_kernel<<<(nW4 + 255) / 256, 256>>>(Wk, pwh, pwl, nW4);
    gemm_bf16x3<<<gg, 256>>>(pah, pal, pwh, pwl, pk);
    // V
    split_kernel<<<(nW4 + 255) / 256, 256>>>(Wv, pwh, pwl, nW4);
    gemm_bf16x3<<<gg, 256>>>(pah, pal, pwh, pwl, pv);

    // attention (fused bias + rope), writes bf16 split into g_ahi/g_alo
    const int smem = (3 * WIN * HDP + WIN * SCP) * (int)sizeof(float);  // 81,152 B
    cudaFuncSetAttribute(attn_win, cudaFuncAttributeMaxDynamicSharedMemorySize, smem);
    attn_win<<<dim3(NWIN, NH), 256, smem>>>(cosp, sinp, bq, bk, bv);

    // output projection
    split_kernel<<<(nW4 + 255) / 256, 256>>>(Wp, pwh, pwl, nW4);
    gemm_bf16x3<<<gg, 256>>>(pah, pal, pwh, pwl, out);
    bias_add<<<nA4 / 256, 256>>>(out, bp);
}

// round 4
// speedup vs baseline: 4.6116x; 2.3289x over previous
#include <cuda_runtime.h>
#include <cuda_bf16.h>
#include <mma.h>
#include <cstdint>

#define SEQ   16384
#define DIM   1280
#define NH    16
#define HD    80
#define WIN   64
#define NWIN  (SEQ / WIN)
#define HDP   84
#define SCP   65

// tcgen05 GEMM tiling
#define TM    128          // CTA tile M
#define TN    256          // CTA tile N
#define TKB   128          // K-chunk bytes per row (64 bf16) = SW128 row
#define TKE   64           // K-chunk elements
#define NSTG  (DIM / TKE)  // 20 k-stages

// smem layout (dynamic)
#define SM_TMEM   0
#define SM_MBAR0  8
#define SM_BUF    1024
#define A_BYTES   (TM * TKB)                 // 16384
#define B_BYTES   (TN * TKB)                 // 32768
#define STAGE_BYTES (2*A_BYTES + 2*B_BYTES)  // 96 KB
#define SMEM_GEMM (SM_BUF + 2 * STAGE_BYTES) // 197,632 B

// Arch-specific tcgen05 (TMEM ld/st) only exists on sm_10xa targets.
#if defined(__CUDA_ARCH__) && (defined(__CUDA_ARCH_FEAT_SM103_ALL) || defined(__CUDA_ARCH_FEAT_SM100_ALL))
#define TC_PATH 1
#else
#define TC_PATH 0
#endif

// ---------------------------------------------------------------------------
// Scratch
// ---------------------------------------------------------------------------
__device__ float g_q[SEQ * DIM];
__device__ float g_k[SEQ * DIM];
__device__ float g_v[SEQ * DIM];
__device__ __nv_bfloat16 g_ahi[SEQ * DIM];
__device__ __nv_bfloat16 g_alo[SEQ * DIM];
__device__ __nv_bfloat16 g_whi[DIM * DIM];
__device__ __nv_bfloat16 g_wlo[DIM * DIM];

#if TC_PATH
// ---------------------------------------------------------------------------
// PTX helpers (sm_103a only)
// ---------------------------------------------------------------------------
__device__ __forceinline__ uint32_t smem_u32(const void* p) {
    uint32_t a;
    asm("{ .reg .u64 t; cvta.to.shared.u64 t, %1; cvt.u32.u64 %0, t; }"
        : "=r"(a) : "l"(p));
    return a;
}

__device__ __forceinline__ uint32_t elect_one() {
    uint32_t p;
    asm volatile("{ .reg .pred P; elect.sync _|P, 0xFFFFFFFF; selp.b32 %0, 1, 0, P; }"
                 : "=r"(p));
    return p;
}

#define MBAR_INIT(addr, cnt) \
    asm volatile("mbarrier.init.shared.b64 [%0], %1;" :: "r"(addr), "r"(cnt) : "memory")

__device__ __forceinline__ void mbar_wait(uint32_t mbar, uint32_t phase) {
    asm volatile(
        "{\n\t.reg .pred P;\n\t"
        "WL_%=:\n\t"
        "mbarrier.try_wait.parity.acquire.cta.shared::cta.b64 P, [%0], %1, 0x989680;\n\t"
        "@P bra WD_%=;\n\t"
        "bra WL_%=;\n\t"
        "WD_%=:\n\t}"
        :: "r"(mbar), "r"(phase) : "memory");
}

#define FENCE_ASYNC() asm volatile("fence.proxy.async.shared::cta;" ::: "memory")

// SW128 K-major smem descriptor: layout=2, version=1, SBO=64, LBO=1
__device__ __forceinline__ uint64_t mk_desc(uint32_t addr) {
    return ((uint64_t)2 << 61) | ((uint64_t)1 << 46) | ((uint64_t)64 << 32) |
           ((uint64_t)1 << 16) | (uint64_t)((addr >> 4) & 0x3FFF);
}

__device__ __forceinline__ void mma_bf16_ss(uint32_t d, uint64_t ad, uint64_t bd,
                                            uint32_t idesc, uint32_t en) {
    asm volatile(
        "{\n\t.reg .pred p;\n\tsetp.ne.u32 p, %5, 0;\n\t"
        "tcgen05.mma.cta_group::1.kind::f16 [%0], %1, %2, %3, {%4, %4, %4, %4}, p;\n\t}"
        :: "r"(d), "l"(ad), "l"(bd), "r"(idesc), "r"(0u), "r"(en) : "memory");
}

#define TC_COMMIT(mbar) \
    asm volatile("tcgen05.commit.cta_group::1.mbarrier::arrive::one.shared::cluster.b64 [%0];" \
                 :: "r"(mbar) : "memory")
#define TC_ALLOC(slot, n) \
    asm volatile("tcgen05.alloc.cta_group::1.sync.aligned.shared::cta.b32 [%0], %1;" \
                 :: "r"(slot), "r"(n) : "memory")
#define TC_RELINQ() \
    asm volatile("tcgen05.relinquish_alloc_permit.cta_group::1.sync.aligned;")
#define TC_DEALLOC(t, n) \
    asm volatile("tcgen05.dealloc.cta_group::1.sync.aligned.b32 %0, %1;" :: "r"(t), "r"(n))
#define TC_FENCE_AFTER()  asm volatile("tcgen05.fence::after_thread_sync;" ::: "memory")
#define TC_FENCE_BEFORE() asm volatile("tcgen05.fence::before_thread_sync;" ::: "memory")
#define TC_WAIT_LD() asm volatile("tcgen05.wait::ld.sync.aligned;" ::: "memory")

#define LDTM_X32(r, addr) \
    asm volatile("tcgen05.ld.sync.aligned.32x32b.x32.b32 " \
        "{%0,%1,%2,%3,%4,%5,%6,%7,%8,%9,%10,%11,%12,%13,%14,%15," \
        "%16,%17,%18,%19,%20,%21,%22,%23,%24,%25,%26,%27,%28,%29,%30,%31}, [%32];" \
        : "=r"((r)[0]),"=r"((r)[1]),"=r"((r)[2]),"=r"((r)[3]), \
          "=r"((r)[4]),"=r"((r)[5]),"=r"((r)[6]),"=r"((r)[7]), \
          "=r"((r)[8]),"=r"((r)[9]),"=r"((r)[10]),"=r"((r)[11]), \
          "=r"((r)[12]),"=r"((r)[13]),"=r"((r)[14]),"=r"((r)[15]), \
          "=r"((r)[16]),"=r"((r)[17]),"=r"((r)[18]),"=r"((r)[19]), \
          "=r"((r)[20]),"=r"((r)[21]),"=r"((r)[22]),"=r"((r)[23]), \
          "=r"((r)[24]),"=r"((r)[25]),"=r"((r)[26]),"=r"((r)[27]), \
          "=r"((r)[28]),"=r"((r)[29]),"=r"((r)[30]),"=r"((r)[31]) \
        : "r"(addr))

// idesc: fp32 accum, bf16 a/b, N=256, M=128
#define IDESC ((1u << 4) | (1u << 7) | (1u << 10) | ((TN / 8) << 17) | ((TM / 16) << 24))
#endif  // TC_PATH

// ---------------------------------------------------------------------------
// fp32 -> bf16 hi + residual lo
// ---------------------------------------------------------------------------
__global__ void split_kernel(const float* __restrict__ src,
                             __nv_bfloat16* __restrict__ hi,
                             __nv_bfloat16* __restrict__ lo, int n4)
{
    int i = blockIdx.x * blockDim.x + threadIdx.x;
    if (i >= n4) return;
    float4 v = ((const float4*)src)[i];
    __nv_bfloat16 h0 = __float2bfloat16(v.x);
    __nv_bfloat16 h1 = __float2bfloat16(v.y);
    __nv_bfloat16 h2 = __float2bfloat16(v.z);
    __nv_bfloat16 h3 = __float2bfloat16(v.w);
    __nv_bfloat16 l0 = __float2bfloat16(v.x - __bfloat162float(h0));
    __nv_bfloat16 l1 = __float2bfloat16(v.y - __bfloat162float(h1));
    __nv_bfloat16 l2 = __float2bfloat16(v.z - __bfloat162float(h2));
    __nv_bfloat16 l3 = __float2bfloat16(v.w - __bfloat162float(h3));
    __nv_bfloat162* hp = (__nv_bfloat162*)hi;
    __nv_bfloat162* lp = (__nv_bfloat162*)lo;
    hp[2 * i]     = __nv_bfloat162(h0, h1);
    hp[2 * i + 1] = __nv_bfloat162(h2, h3);
    lp[2 * i]     = __nv_bfloat162(l0, l1);
    lp[2 * i + 1] = __nv_bfloat162(l2, l3);
}

// ---------------------------------------------------------------------------
// bf16x3 GEMM: C[M,N] = (Ah+Al)[M,K] @ (Bh+Bl)[N,K]^T
// grid (DIM/TN, SEQ/TM) = (5, 128), 256 threads.
// sm_103a image: tcgen05 double-buffered pipeline.
// family/generic image: wmma fallback (correct, slower; only used if JIT'd).
// ---------------------------------------------------------------------------
__global__ __launch_bounds__(256, 1)
void gemm_tc(const __nv_bfloat16* __restrict__ Ah,
             const __nv_bfloat16* __restrict__ Al,
             const __nv_bfloat16* __restrict__ Bh,
             const __nv_bfloat16* __restrict__ Bl,
             float* __restrict__ C)
{
    extern __shared__ char smc[];
    const int tid = threadIdx.x;
    const int wid = tid >> 5;
    const int bm = blockIdx.y * TM;
    const int bn = blockIdx.x * TN;

#if TC_PATH
    const int lane = tid & 31;
    const uint32_t sbase = smem_u32(smc);

    if (tid == 0) {
        MBAR_INIT(sbase + SM_MBAR0, 1);
        MBAR_INIT(sbase + SM_MBAR0 + 8, 1);
    }
    if (wid == 0) {
        TC_ALLOC(sbase + SM_TMEM, 256);
        TC_RELINQ();
    }
    __syncthreads();

    uint32_t tmem;
    asm volatile("ld.shared.b32 %0, [%1];" : "=r"(tmem) : "r"(sbase + SM_TMEM));

    auto load_stage = [&](int i, int b) {
        char* buf = smc + SM_BUF + b * STAGE_BYTES;
        char* sAh = buf;
        char* sAl = buf + A_BYTES;
        char* sBh = buf + 2 * A_BYTES;
        char* sBl = buf + 2 * A_BYTES + B_BYTES;
        const int k0 = i * TKE;
#pragma unroll
        for (int r = 0; r < 4; r++) {               // A: 128 rows x 8 chunks
            int id = tid + r * 256;
            int row = id >> 3, c = id & 7;
            size_t g = (size_t)(bm + row) * DIM + k0 + c * 8;
            uint32_t off = row * TKB + c * 16;
            uint32_t sw = off ^ ((off >> 3) & 0x70);
            *(uint4*)(sAh + sw) = *(const uint4*)(Ah + g);
            *(uint4*)(sAl + sw) = *(const uint4*)(Al + g);
        }
#pragma unroll
        for (int r = 0; r < 8; r++) {               // B: 256 rows x 8 chunks
            int id = tid + r * 256;
            int row = id >> 3, c = id & 7;
            size_t g = (size_t)(bn + row) * DIM + k0 + c * 8;
            uint32_t off = row * TKB + c * 16;
            uint32_t sw = off ^ ((off >> 3) & 0x70);
            *(uint4*)(sBh + sw) = *(const uint4*)(Bh + g);
            *(uint4*)(sBl + sw) = *(const uint4*)(Bl + g);
        }
        FENCE_ASYNC();
    };

    load_stage(0, 0);

    int par[2] = {0, 0};

    for (int i = 0; i < NSTG; i++) {
        const int b = i & 1;
        __syncthreads();   // stage-i loads visible

        if (wid == 0 && elect_one()) {
            const uint32_t bufb = sbase + SM_BUF + b * STAGE_BYTES;
            uint64_t adh = mk_desc(bufb);
            uint64_t adl = mk_desc(bufb + A_BYTES);
            uint64_t bdh = mk_desc(bufb + 2 * A_BYTES);
            uint64_t bdl = mk_desc(bufb + 2 * A_BYTES + B_BYTES);
#pragma unroll
            for (int ks = 0; ks < 4; ks++) {
                mma_bf16_ss(tmem, adh + 2 * ks, bdh + 2 * ks, IDESC,
                            (i == 0 && ks == 0) ? 0u : 1u);
                mma_bf16_ss(tmem, adh + 2 * ks, bdl + 2 * ks, IDESC, 1u);
                mma_bf16_ss(tmem, adl + 2 * ks, bdh + 2 * ks, IDESC, 1u);
            }
            TC_COMMIT(sbase + SM_MBAR0 + 8 * b);
        }

        if (i + 1 < NSTG) {
            const int j = b ^ 1;
            if (i >= 1) {   // buffer j's previous MMA (stage i-1) must retire
                mbar_wait(sbase + SM_MBAR0 + 8 * j, par[j]);
                par[j] ^= 1;
            }
            load_stage(i + 1, j);
        }
    }

    mbar_wait(sbase + SM_MBAR0 + 8 * ((NSTG - 1) & 1), par[(NSTG - 1) & 1]);
    TC_FENCE_AFTER();

    // epilogue: warps 0-3 each read their 32-row TMEM subpartition
    if (wid < 4) {
        float* crow = C + (size_t)(bm + wid * 32 + lane) * DIM + bn;
#pragma unroll
        for (int cc = 0; cc < 8; cc++) {
            uint32_t r[32];
            LDTM_X32(r, tmem + cc * 32);
            TC_WAIT_LD();
            uint4* cp = (uint4*)(crow + cc * 32);
#pragma unroll
            for (int q = 0; q < 8; q++)
                cp[q] = make_uint4(r[4 * q], r[4 * q + 1], r[4 * q + 2], r[4 * q + 3]);
        }
        TC_FENCE_BEFORE();
    }

    __syncthreads();
    if (wid == 0) TC_DEALLOC(tmem, 256);

#else  // ------- wmma fallback (family/generic targets; correctness net) -----
    using namespace nvcuda;
    const int GLDS = 40;
    __nv_bfloat16* sAh = (__nv_bfloat16*)smc;                    // 128*40
    __nv_bfloat16* sAl = sAh + 128 * GLDS;
    __nv_bfloat16* sBh = sAl + 128 * GLDS;
    __nv_bfloat16* sBl = sBh + 128 * GLDS;

    const int warp = wid;
    const int wm = (warp & 1) * 64;
    const int wn = (warp >> 1) * 32;
    const int r0 = tid >> 2;
    const int c0 = (tid & 3) * 8;

    for (int half = 0; half < 2; half++) {
        const int bnh = bn + half * 128;
        wmma::fragment<wmma::accumulator, 16, 16, 16, float> acc[4][2];
#pragma unroll
        for (int i = 0; i < 4; i++)
#pragma unroll
            for (int j = 0; j < 2; j++) wmma::fill_fragment(acc[i][j], 0.0f);

        for (int k0 = 0; k0 < DIM; k0 += 32) {
            __syncthreads();
#pragma unroll
            for (int rr = 0; rr < 2; rr++) {
                int row = r0 + rr * 64;
                size_t ga = (size_t)(bm + row) * DIM + k0 + c0;
                size_t gb = (size_t)(bnh + row) * DIM + k0 + c0;
                *(uint4*)&sAh[row * GLDS + c0] = *(const uint4*)(Ah + ga);
                *(uint4*)&sAl[row * GLDS + c0] = *(const uint4*)(Al + ga);
                *(uint4*)&sBh[row * GLDS + c0] = *(const uint4*)(Bh + gb);
                *(uint4*)&sBl[row * GLDS + c0] = *(const uint4*)(Bl + gb);
            }
            __syncthreads();
#pragma unroll
            for (int kk = 0; kk < 32; kk += 16) {
                wmma::fragment<wmma::matrix_a, 16, 16, 16, __nv_bfloat16, wmma::row_major> fah[4], fal[4];
                wmma::fragment<wmma::matrix_b, 16, 16, 16, __nv_bfloat16, wmma::col_major> fbh[2], fbl[2];
#pragma unroll
                for (int i = 0; i < 4; i++) {
                    wmma::load_matrix_sync(fah[i], &sAh[(wm + i * 16) * GLDS + kk], GLDS);
                    wmma::load_matrix_sync(fal[i], &sAl[(wm + i * 16) * GLDS + kk], GLDS);
                }
#pragma unroll
                for (int j = 0; j < 2; j++) {
                    wmma::load_matrix_sync(fbh[j], &sBh[(wn + j * 16) * GLDS + kk], GLDS);
                    wmma::load_matrix_sync(fbl[j], &sBl[(wn + j * 16) * GLDS + kk], GLDS);
                }
#pragma unroll
                for (int i = 0; i < 4; i++)
#pragma unroll
                    for (int j = 0; j < 2; j++) {
                        wmma::mma_sync(acc[i][j], fah[i], fbh[j], acc[i][j]);
                        wmma::mma_sync(acc[i][j], fah[i], fbl[j], acc[i][j]);
                        wmma::mma_sync(acc[i][j], fal[i], fbh[j], acc[i][j]);
                    }
            }
        }
#pragma unroll
        for (int i = 0; i < 4; i++)
#pragma unroll
            for (int j = 0; j < 2; j++)
                wmma::store_matrix_sync(&C[(size_t)(bm + wm + i * 16) * DIM + bnh + wn + j * 16],
                                        acc[i][j], DIM, wmma::mem_row_major);
        __syncthreads();
    }
#endif
}

// ---------------------------------------------------------------------------
// Windowed attention, fused bias + RoPE; writes bf16 hi/lo split
// ---------------------------------------------------------------------------
__global__ __launch_bounds__(256)
void attn_win(const float* __restrict__ cosp, const float* __restrict__ sinp,
              const float* __restrict__ bq, const float* __restrict__ bk,
              const float* __restrict__ bv)
{
    extern __shared__ float sm[];
    float* qs = sm;
    float* ks = qs + WIN * HDP;
    float* vs = ks + WIN * HDP;
    float* sc = vs + WIN * HDP;

    const int w = blockIdx.x;
    const int h = blockIdx.y;
    const int tid = threadIdx.x;
    const size_t base = (size_t)(w * WIN) * DIM + (size_t)h * HD;

    for (int idx = tid; idx < WIN * (HD / 2); idx += 256) {
        int row = idx / (HD / 2);
        int d   = idx % (HD / 2);
        int s   = w * WIN + row;
        float c1 = cosp[s * HD + d],          s1 = sinp[s * HD + d];
        float c2 = cosp[s * HD + d + HD / 2], s2 = sinp[s * HD + d + HD / 2];
        size_t o1 = base + (size_t)row * DIM + d;
        size_t o2 = o1 + HD / 2;

        float q1 = g_q[o1] + bq[h * HD + d];
        float q2 = g_q[o2] + bq[h * HD + d + HD / 2];
        qs[row * HDP + d]          = q1 * c1 - q2 * s1;
        qs[row * HDP + d + HD / 2] = q2 * c2 + q1 * s2;

        float k1 = g_k[o1] + bk[h * HD + d];
        float k2 = g_k[o2] + bk[h * HD + d + HD / 2];
        ks[row * HDP + d]          = k1 * c1 - k2 * s1;
        ks[row * HDP + d + HD / 2] = k2 * c2 + k1 * s2;
    }
    for (int idx = tid; idx < WIN * (HD / 4); idx += 256) {
        int row = idx / (HD / 4);
        int col = (idx % (HD / 4)) * 4;
        size_t g = base + (size_t)row * DIM + col;
        float4 vv = *(const float4*)(g_v + g);
        vv.x += bv[h * HD + col + 0];
        vv.y += bv[h * HD + col + 1];
        vv.z += bv[h * HD + col + 2];
        vv.w += bv[h * HD + col + 3];
        *(float4*)(vs + row * HDP + col) = vv;
    }
    __syncthreads();

    const float scale = 0.11180339887498949f;
    {
        const int i  = tid & 63;
        const int jb = (tid >> 6) * 16;
        for (int j = jb; j < jb + 16; j++) {
            float s = 0.f;
#pragma unroll
            for (int d = 0; d < HD; d += 4) {
                float4 qv = *(const float4*)(qs + i * HDP + d);
                float4 kv = *(const float4*)(ks + j * HDP + d);
                s += qv.x * kv.x + qv.y * kv.y + qv.z * kv.z + qv.w * kv.w;
            }
            sc[i * SCP + j] = s * scale;
        }
    }
    __syncthreads();

    if (tid < WIN) {
        float m = -1e30f;
        for (int j = 0; j < WIN; j++) m = fmaxf(m, sc[tid * SCP + j]);
        float sum = 0.f;
        for (int j = 0; j < WIN; j++) {
            float e = __expf(sc[tid * SCP + j] - m);
            sc[tid * SCP + j] = e;
            sum += e;
        }
        float inv = 1.f / sum;
        for (int j = 0; j < WIN; j++) sc[tid * SCP + j] *= inv;
    }
    __syncthreads();

    for (int idx = tid; idx < WIN * HD; idx += 256) {
        int i = idx / HD;
        int d = idx % HD;
        float s = 0.f;
#pragma unroll 8
        for (int j = 0; j < WIN; j++)
            s += sc[i * SCP + j] * vs[j * HDP + d];
        size_t o = base + (size_t)i * DIM + d;
        __nv_bfloat16 hi = __float2bfloat16(s);
        g_ahi[o] = hi;
        g_alo[o] = __float2bfloat16(s - __bfloat162float(hi));
    }
}

// ---------------------------------------------------------------------------
__global__ void bias_add(float* __restrict__ out, const float* __restrict__ bp)
{
    int i = blockIdx.x * blockDim.x + threadIdx.x;
    float4 v = ((float4*)out)[i];
    int col = (i * 4) % DIM;
    v.x += bp[col + 0];
    v.y += bp[col + 1];
    v.z += bp[col + 2];
    v.w += bp[col + 3];
    ((float4*)out)[i] = v;
}

// ---------------------------------------------------------------------------
extern "C" void kernel_launch(void* const* d_in, const int* in_sizes, int n_in,
                              void* d_out, int out_size)
{
    const float* hs   = (const float*)d_in[0];
    const float* cosp = (const float*)d_in[1];
    const float* sinp = (const float*)d_in[2];
    const float* Wq   = (const float*)d_in[3];
    const float* bq   = (const float*)d_in[4];
    const float* Wk   = (const float*)d_in[5];
    const float* bk   = (const float*)d_in[6];
    const float* Wv   = (const float*)d_in[7];
    const float* bv   = (const float*)d_in[8];
    const float* Wp   = (const float*)d_in[9];
    const float* bp   = (const float*)d_in[10];
    float* out = (float*)d_out;

    float *pq, *pk, *pv;
    __nv_bfloat16 *pah, *pal, *pwh, *pwl;
    cudaGetSymbolAddress((void**)&pq,  g_q);
    cudaGetSymbolAddress((void**)&pk,  g_k);
    cudaGetSymbolAddress((void**)&pv,  g_v);
    cudaGetSymbolAddress((void**)&pah, g_ahi);
    cudaGetSymbolAddress((void**)&pal, g_alo);
    cudaGetSymbolAddress((void**)&pwh, g_whi);
    cudaGetSymbolAddress((void**)&pwl, g_wlo);

    const int nA4 = SEQ * DIM / 4;
    const int nW4 = DIM * DIM / 4;
    dim3 gg(DIM / TN, SEQ / TM);   // (5, 128)

    cudaFuncSetAttribute(gemm_tc, cudaFuncAttributeMaxDynamicSharedMemorySize, SMEM_GEMM);

    split_kernel<<<(nA4 + 255) / 256, 256>>>(hs, pah, pal, nA4);

    split_kernel<<<(nW4 + 255) / 256, 256>>>(Wq, pwh, pwl, nW4);
    gemm_tc<<<gg, 256, SMEM_GEMM>>>(pah, pal, pwh, pwl, pq);
    split_kernel<<<(nW4 + 255) / 256, 256>>>(Wk, pwh, pwl, nW4);
    gemm_tc<<<gg, 256, SMEM_GEMM>>>(pah, pal, pwh, pwl, pk);
    split_kernel<<<(nW4 + 255) / 256, 256>>>(Wv, pwh, pwl, nW4);
    gemm_tc<<<gg, 256, SMEM_GEMM>>>(pah, pal, pwh, pwl, pv);

    const int smem = (3 * WIN * HDP + WIN * SCP) * (int)sizeof(float);
    cudaFuncSetAttribute(attn_win, cudaFuncAttributeMaxDynamicSharedMemorySize, smem);
    attn_win<<<dim3(NWIN, NH), 256, smem>>>(cosp, sinp, bq, bk, bv);

    split_kernel<<<(nW4 + 255) / 256, 256>>>(Wp, pwh, pwl, nW4);
    gemm_tc<<<gg, 256, SMEM_GEMM>>>(pah, pal, pwh, pwl, out);
    bias_add<<<nA4 / 256, 256>>>(out, bp);
}

// round 5
// speedup vs baseline: 5.1585x; 1.1186x over previous
#include <cuda_runtime.h>
#include <cuda_bf16.h>
#include <mma.h>
#include <cstdint>

#define SEQ   16384
#define DIM   1280
#define NH    16
#define HD    80
#define WIN   64
#define NWIN  (SEQ / WIN)
#define HDP   84
#define SCP   65

// tcgen05 GEMM tiling
#define TM    128          // CTA tile M
#define TN    256          // CTA tile N
#define TKB   128          // K-chunk bytes per row (64 bf16) = SW128 row
#define TKE   64           // K-chunk elements
#define NSTG  (DIM / TKE)  // 20 k-stages

// smem layout (dynamic)
#define SM_TMEM   0
#define SM_MBAR0  8
#define SM_BUF    1024
#define A_BYTES   (TM * TKB)                 // 16384
#define B_BYTES   (TN * TKB)                 // 32768
#define STAGE_BYTES (2*A_BYTES + 2*B_BYTES)  // 96 KB
#define SMEM_GEMM (SM_BUF + 2 * STAGE_BYTES) // 197,632 B

// Arch-specific tcgen05 (TMEM ld/st) only exists on sm_10xa targets.
#if defined(__CUDA_ARCH__) && (defined(__CUDA_ARCH_FEAT_SM103_ALL) || defined(__CUDA_ARCH_FEAT_SM100_ALL))
#define TC_PATH 1
#else
#define TC_PATH 0
#endif

// ---------------------------------------------------------------------------
// Scratch
// ---------------------------------------------------------------------------
__device__ float g_q[SEQ * DIM];
__device__ float g_k[SEQ * DIM];
__device__ float g_v[SEQ * DIM];
__device__ __nv_bfloat16 g_ahi[SEQ * DIM];
__device__ __nv_bfloat16 g_alo[SEQ * DIM];
__device__ __nv_bfloat16 g_whi[DIM * DIM];
__device__ __nv_bfloat16 g_wlo[DIM * DIM];

#if TC_PATH
// ---------------------------------------------------------------------------
// PTX helpers (sm_103a only)
// ---------------------------------------------------------------------------
__device__ __forceinline__ uint32_t smem_u32(const void* p) {
    uint32_t a;
    asm("{ .reg .u64 t; cvta.to.shared.u64 t, %1; cvt.u32.u64 %0, t; }"
        : "=r"(a) : "l"(p));
    return a;
}

__device__ __forceinline__ uint32_t elect_one() {
    uint32_t p;
    asm volatile("{ .reg .pred P; elect.sync _|P, 0xFFFFFFFF; selp.b32 %0, 1, 0, P; }"
                 : "=r"(p));
    return p;
}

#define MBAR_INIT(addr, cnt) \
    asm volatile("mbarrier.init.shared.b64 [%0], %1;" :: "r"(addr), "r"(cnt) : "memory")

__device__ __forceinline__ void mbar_wait(uint32_t mbar, uint32_t phase) {
    asm volatile(
        "{\n\t.reg .pred P;\n\t"
        "WL_%=:\n\t"
        "mbarrier.try_wait.parity.acquire.cta.shared::cta.b64 P, [%0], %1, 0x989680;\n\t"
        "@P bra WD_%=;\n\t"
        "bra WL_%=;\n\t"
        "WD_%=:\n\t}"
        :: "r"(mbar), "r"(phase) : "memory");
}

#define FENCE_ASYNC() asm volatile("fence.proxy.async.shared::cta;" ::: "memory")

// async 16B copy global -> shared (L1-bypass)
__device__ __forceinline__ void cp16(uint32_t saddr, const void* gptr) {
    asm volatile("cp.async.cg.shared.global [%0], [%1], 16;"
                 :: "r"(saddr), "l"(gptr) : "memory");
}
#define CP_COMMIT() asm volatile("cp.async.commit_group;" ::: "memory")
#define CP_WAIT1()  asm volatile("cp.async.wait_group 1;" ::: "memory")
#define CP_WAIT0()  asm volatile("cp.async.wait_group 0;" ::: "memory")

// SW128 K-major smem descriptor: layout=2, version=1, SBO=64, LBO=1
__device__ __forceinline__ uint64_t mk_desc(uint32_t addr) {
    return ((uint64_t)2 << 61) | ((uint64_t)1 << 46) | ((uint64_t)64 << 32) |
           ((uint64_t)1 << 16) | (uint64_t)((addr >> 4) & 0x3FFF);
}

__device__ __forceinline__ void mma_bf16_ss(uint32_t d, uint64_t ad, uint64_t bd,
                                            uint32_t idesc, uint32_t en) {
    asm volatile(
        "{\n\t.reg .pred p;\n\tsetp.ne.u32 p, %5, 0;\n\t"
        "tcgen05.mma.cta_group::1.kind::f16 [%0], %1, %2, %3, {%4, %4, %4, %4}, p;\n\t}"
        :: "r"(d), "l"(ad), "l"(bd), "r"(idesc), "r"(0u), "r"(en) : "memory");
}

#define TC_COMMIT(mbar) \
    asm volatile("tcgen05.commit.cta_group::1.mbarrier::arrive::one.shared::cluster.b64 [%0];" \
                 :: "r"(mbar) : "memory")
#define TC_ALLOC(slot, n) \
    asm volatile("tcgen05.alloc.cta_group::1.sync.aligned.shared::cta.b32 [%0], %1;" \
                 :: "r"(slot), "r"(n) : "memory")
#define TC_RELINQ() \
    asm volatile("tcgen05.relinquish_alloc_permit.cta_group::1.sync.aligned;")
#define TC_DEALLOC(t, n) \
    asm volatile("tcgen05.dealloc.cta_group::1.sync.aligned.b32 %0, %1;" :: "r"(t), "r"(n))
#define TC_FENCE_AFTER()  asm volatile("tcgen05.fence::after_thread_sync;" ::: "memory")
#define TC_FENCE_BEFORE() asm volatile("tcgen05.fence::before_thread_sync;" ::: "memory")
#define TC_WAIT_LD() asm volatile("tcgen05.wait::ld.sync.aligned;" ::: "memory")

#define LDTM_X32(r, addr) \
    asm volatile("tcgen05.ld.sync.aligned.32x32b.x32.b32 " \
        "{%0,%1,%2,%3,%4,%5,%6,%7,%8,%9,%10,%11,%12,%13,%14,%15," \
        "%16,%17,%18,%19,%20,%21,%22,%23,%24,%25,%26,%27,%28,%29,%30,%31}, [%32];" \
        : "=r"((r)[0]),"=r"((r)[1]),"=r"((r)[2]),"=r"((r)[3]), \
          "=r"((r)[4]),"=r"((r)[5]),"=r"((r)[6]),"=r"((r)[7]), \
          "=r"((r)[8]),"=r"((r)[9]),"=r"((r)[10]),"=r"((r)[11]), \
          "=r"((r)[12]),"=r"((r)[13]),"=r"((r)[14]),"=r"((r)[15]), \
          "=r"((r)[16]),"=r"((r)[17]),"=r"((r)[18]),"=r"((r)[19]), \
          "=r"((r)[20]),"=r"((r)[21]),"=r"((r)[22]),"=r"((r)[23]), \
          "=r"((r)[24]),"=r"((r)[25]),"=r"((r)[26]),"=r"((r)[27]), \
          "=r"((r)[28]),"=r"((r)[29]),"=r"((r)[30]),"=r"((r)[31]) \
        : "r"(addr))

// idesc: fp32 accum, bf16 a/b, N=256, M=128
#define IDESC ((1u << 4) | (1u << 7) | (1u << 10) | ((TN / 8) << 17) | ((TM / 16) << 24))
#endif  // TC_PATH

// ---------------------------------------------------------------------------
// fp32 -> bf16 hi + residual lo
// ---------------------------------------------------------------------------
__global__ void split_kernel(const float* __restrict__ src,
                             __nv_bfloat16* __restrict__ hi,
                             __nv_bfloat16* __restrict__ lo, int n4)
{
    int i = blockIdx.x * blockDim.x + threadIdx.x;
    if (i >= n4) return;
    float4 v = ((const float4*)src)[i];
    __nv_bfloat16 h0 = __float2bfloat16(v.x);
    __nv_bfloat16 h1 = __float2bfloat16(v.y);
    __nv_bfloat16 h2 = __float2bfloat16(v.z);
    __nv_bfloat16 h3 = __float2bfloat16(v.w);
    __nv_bfloat16 l0 = __float2bfloat16(v.x - __bfloat162float(h0));
    __nv_bfloat16 l1 = __float2bfloat16(v.y - __bfloat162float(h1));
    __nv_bfloat16 l2 = __float2bfloat16(v.z - __bfloat162float(h2));
    __nv_bfloat16 l3 = __float2bfloat16(v.w - __bfloat162float(h3));
    __nv_bfloat162* hp = (__nv_bfloat162*)hi;
    __nv_bfloat162* lp = (__nv_bfloat162*)lo;
    hp[2 * i]     = __nv_bfloat162(h0, h1);
    hp[2 * i + 1] = __nv_bfloat162(h2, h3);
    lp[2 * i]     = __nv_bfloat162(l0, l1);
    lp[2 * i + 1] = __nv_bfloat162(l2, l3);
}

// ---------------------------------------------------------------------------
// bf16x3 GEMM: C[M,N] = (Ah+Al)[M,K] @ (Bh+Bl)[N,K]^T
// grid (DIM/TN, SEQ/TM) = (5, 128), 256 threads.
// sm_103a image: tcgen05 + cp.async double-buffered pipeline.
// family/generic image: wmma fallback (correct, slower; only used if JIT'd).
// ---------------------------------------------------------------------------
__global__ __launch_bounds__(256, 1)
void gemm_tc(const __nv_bfloat16* __restrict__ Ah,
             const __nv_bfloat16* __restrict__ Al,
             const __nv_bfloat16* __restrict__ Bh,
             const __nv_bfloat16* __restrict__ Bl,
             float* __restrict__ C)
{
    extern __shared__ char smc[];
    const int tid = threadIdx.x;
    const int wid = tid >> 5;
    const int bm = blockIdx.y * TM;
    const int bn = blockIdx.x * TN;

#if TC_PATH
    const int lane = tid & 31;
    const uint32_t sbase = smem_u32(smc);

    if (tid == 0) {
        MBAR_INIT(sbase + SM_MBAR0, 1);
        MBAR_INIT(sbase + SM_MBAR0 + 8, 1);
    }
    if (wid == 0) {
        TC_ALLOC(sbase + SM_TMEM, 256);
        TC_RELINQ();
    }
    __syncthreads();

    uint32_t tmem;
    asm volatile("ld.shared.b32 %0, [%1];" : "=r"(tmem) : "r"(sbase + SM_TMEM));

    // precomputed per-thread load coordinates
    const int row8 = tid >> 3;          // 0..31  (row group base)
    const int c8   = (tid & 7) * 16;    // byte chunk within 128B row

    // async stage loader: k-chunk i -> buffer b (24 cp.async per thread)
    auto load_async = [&](int i, int b) {
        const uint32_t buf = sbase + SM_BUF + b * STAGE_BYTES;
        const int k0 = i * TKE;
#pragma unroll
        for (int r = 0; r < 4; r++) {               // A: 128 rows
            int row = row8 + r * 32;
            size_t g = (size_t)(bm + row) * DIM + k0 + (c8 >> 1);
            uint32_t off = row * TKB + c8;
            uint32_t sw = off ^ ((off >> 3) & 0x70);
            cp16(buf + sw, Ah + g);
            cp16(buf + A_BYTES + sw, Al + g);
        }
#pragma unroll
        for (int r = 0; r < 8; r++) {               // B: 256 rows
            int row = row8 + r * 32;
            size_t g = (size_t)(bn + row) * DIM + k0 + (c8 >> 1);
            uint32_t off = row * TKB + c8;
            uint32_t sw = off ^ ((off >> 3) & 0x70);
            cp16(buf + 2 * A_BYTES + sw, Bh + g);
            cp16(buf + 2 * A_BYTES + B_BYTES + sw, Bl + g);
        }
        CP_COMMIT();
    };

    load_async(0, 0);

    int par[2] = {0, 0};

    for (int i = 0; i < NSTG; i++) {
        const int b = i & 1;

        if (i + 1 < NSTG) {
            const int b2 = b ^ 1;
            if (i >= 1) {   // buffer b2's previous MMA (stage i-1) must retire
                mbar_wait(sbase + SM_MBAR0 + 8 * b2, par[b2]);
                par[b2] ^= 1;
            }
            load_async(i + 1, b2);
            CP_WAIT1();     // stage i copies complete (group i+1 in flight)
        } else {
            CP_WAIT0();     // last stage: everything complete
        }
        FENCE_ASYNC();
        __syncthreads();    // stage-i data visible to MMA

        if (wid == 0 && elect_one()) {
            const uint32_t bufb = sbase + SM_BUF + b * STAGE_BYTES;
            uint64_t adh = mk_desc(bufb);
            uint64_t adl = mk_desc(bufb + A_BYTES);
            uint64_t bdh = mk_desc(bufb + 2 * A_BYTES);
            uint64_t bdl = mk_desc(bufb + 2 * A_BYTES + B_BYTES);
#pragma unroll
            for (int ks = 0; ks < 4; ks++) {
                mma_bf16_ss(tmem, adh + 2 * ks, bdh + 2 * ks, IDESC,
                            (i == 0 && ks == 0) ? 0u : 1u);
                mma_bf16_ss(tmem, adh + 2 * ks, bdl + 2 * ks, IDESC, 1u);
                mma_bf16_ss(tmem, adl + 2 * ks, bdh + 2 * ks, IDESC, 1u);
            }
            TC_COMMIT(sbase + SM_MBAR0 + 8 * b);
        }
    }

    // wait final MMA (stage NSTG-1)
    mbar_wait(sbase + SM_MBAR0 + 8 * ((NSTG - 1) & 1), par[(NSTG - 1) & 1]);
    TC_FENCE_AFTER();

    // epilogue: warps 0-3 each read their 32-row TMEM subpartition
    if (wid < 4) {
        float* crow = C + (size_t)(bm + wid * 32 + lane) * DIM + bn;
#pragma unroll
        for (int cc = 0; cc < 8; cc++) {
            uint32_t r[32];
            LDTM_X32(r, tmem + cc * 32);
            TC_WAIT_LD();
            uint4* cp = (uint4*)(crow + cc * 32);
#pragma unroll
            for (int q = 0; q < 8; q++)
                cp[q] = make_uint4(r[4 * q], r[4 * q + 1], r[4 * q + 2], r[4 * q + 3]);
        }
        TC_FENCE_BEFORE();
    }

    __syncthreads();
    if (wid == 0) TC_DEALLOC(tmem, 256);

#else  // ------- wmma fallback (family/generic targets; correctness net) -----
    using namespace nvcuda;
    const int GLDS = 40;
    __nv_bfloat16* sAh = (__nv_bfloat16*)smc;                    // 128*40
    __nv_bfloat16* sAl = sAh + 128 * GLDS;
    __nv_bfloat16* sBh = sAl + 128 * GLDS;
    __nv_bfloat16* sBl = sBh + 128 * GLDS;

    const int warp = wid;
    const int wm = (warp & 1) * 64;
    const int wn = (warp >> 1) * 32;
    const int r0 = tid >> 2;
    const int c0 = (tid & 3) * 8;

    for (int half = 0; half < 2; half++) {
        const int bnh = bn + half * 128;
        wmma::fragment<wmma::accumulator, 16, 16, 16, float> acc[4][2];
#pragma unroll
        for (int i = 0; i < 4; i++)
#pragma unroll
            for (int j = 0; j < 2; j++) wmma::fill_fragment(acc[i][j], 0.0f);

        for (int k0 = 0; k0 < DIM; k0 += 32) {
            __syncthreads();
#pragma unroll
            for (int rr = 0; rr < 2; rr++) {
                int row = r0 + rr * 64;
                size_t ga = (size_t)(bm + row) * DIM + k0 + c0;
                size_t gb = (size_t)(bnh + row) * DIM + k0 + c0;
                *(uint4*)&sAh[row * GLDS + c0] = *(const uint4*)(Ah + ga);
                *(uint4*)&sAl[row * GLDS + c0] = *(const uint4*)(Al + ga);
                *(uint4*)&sBh[row * GLDS + c0] = *(const uint4*)(Bh + gb);
                *(uint4*)&sBl[row * GLDS + c0] = *(const uint4*)(Bl + gb);
            }
            __syncthreads();
#pragma unroll
            for (int kk = 0; kk < 32; kk += 16) {
                wmma::fragment<wmma::matrix_a, 16, 16, 16, __nv_bfloat16, wmma::row_major> fah[4], fal[4];
                wmma::fragment<wmma::matrix_b, 16, 16, 16, __nv_bfloat16, wmma::col_major> fbh[2], fbl[2];
#pragma unroll
                for (int i = 0; i < 4; i++) {
                    wmma::load_matrix_sync(fah[i], &sAh[(wm + i * 16) * GLDS + kk], GLDS);
                    wmma::load_matrix_sync(fal[i], &sAl[(wm + i * 16) * GLDS + kk], GLDS);
                }
#pragma unroll
                for (int j = 0; j < 2; j++) {
                    wmma::load_matrix_sync(fbh[j], &sBh[(wn + j * 16) * GLDS + kk], GLDS);
                    wmma::load_matrix_sync(fbl[j], &sBl[(wn + j * 16) * GLDS + kk], GLDS);
                }
#pragma unroll
                for (int i = 0; i < 4; i++)
#pragma unroll
                    for (int j = 0; j < 2; j++) {
                        wmma::mma_sync(acc[i][j], fah[i], fbh[j], acc[i][j]);
                        wmma::mma_sync(acc[i][j], fah[i], fbl[j], acc[i][j]);
                        wmma::mma_sync(acc[i][j], fal[i], fbh[j], acc[i][j]);
                    }
            }
        }
#pragma unroll
        for (int i = 0; i < 4; i++)
#pragma unroll
            for (int j = 0; j < 2; j++)
                wmma::store_matrix_sync(&C[(size_t)(bm + wm + i * 16) * DIM + bnh + wn + j * 16],
                                        acc[i][j], DIM, wmma::mem_row_major);
        __syncthreads();
    }
#endif
}

// ---------------------------------------------------------------------------
// Windowed attention, fused bias + RoPE; writes bf16 hi/lo split
// ---------------------------------------------------------------------------
__global__ __launch_bounds__(256)
void attn_win(const float* __restrict__ cosp, const float* __restrict__ sinp,
              const float* __restrict__ bq, const float* __restrict__ bk,
              const float* __restrict__ bv)
{
    extern __shared__ float sm[];
    float* qs = sm;
    float* ks = qs + WIN * HDP;
    float* vs = ks + WIN * HDP;
    float* sc = vs + WIN * HDP;

    const int w = blockIdx.x;
    const int h = blockIdx.y;
    const int tid = threadIdx.x;
    const size_t base = (size_t)(w * WIN) * DIM + (size_t)h * HD;

    for (int idx = tid; idx < WIN * (HD / 2); idx += 256) {
        int row = idx / (HD / 2);
        int d   = idx % (HD / 2);
        int s   = w * WIN + row;
        float c1 = cosp[s * HD + d],          s1 = sinp[s * HD + d];
        float c2 = cosp[s * HD + d + HD / 2], s2 = sinp[s * HD + d + HD / 2];
        size_t o1 = base + (size_t)row * DIM + d;
        size_t o2 = o1 + HD / 2;

        float q1 = g_q[o1] + bq[h * HD + d];
        float q2 = g_q[o2] + bq[h * HD + d + HD / 2];
        qs[row * HDP + d]          = q1 * c1 - q2 * s1;
        qs[row * HDP + d + HD / 2] = q2 * c2 + q1 * s2;

        float k1 = g_k[o1] + bk[h * HD + d];
        float k2 = g_k[o2] + bk[h * HD + d + HD / 2];
        ks[row * HDP + d]          = k1 * c1 - k2 * s1;
        ks[row * HDP + d + HD / 2] = k2 * c2 + k1 * s2;
    }
    for (int idx = tid; idx < WIN * (HD / 4); idx += 256) {
        int row = idx / (HD / 4);
        int col = (idx % (HD / 4)) * 4;
        size_t g = base + (size_t)row * DIM + col;
        float4 vv = *(const float4*)(g_v + g);
        vv.x += bv[h * HD + col + 0];
        vv.y += bv[h * HD + col + 1];
        vv.z += bv[h * HD + col + 2];
        vv.w += bv[h * HD + col + 3];
        *(float4*)(vs + row * HDP + col) = vv;
    }
    __syncthreads();

    const float scale = 0.11180339887498949f;
    {
        const int i  = tid & 63;
        const int jb = (tid >> 6) * 16;
        for (int j = jb; j < jb + 16; j++) {
            float s = 0.f;
#pragma unroll
            for (int d = 0; d < HD; d += 4) {
                float4 qv = *(const float4*)(qs + i * HDP + d);
                float4 kv = *(const float4*)(ks + j * HDP + d);
                s += qv.x * kv.x + qv.y * kv.y + qv.z * kv.z + qv.w * kv.w;
            }
            sc[i * SCP + j] = s * scale;
        }
    }
    __syncthreads();

    if (tid < WIN) {
        float m = -1e30f;
        for (int j = 0; j < WIN; j++) m = fmaxf(m, sc[tid * SCP + j]);
        float sum = 0.f;
        for (int j = 0; j < WIN; j++) {
            float e = __expf(sc[tid * SCP + j] - m);
            sc[tid * SCP + j] = e;
            sum += e;
        }
        float inv = 1.f / sum;
        for (int j = 0; j < WIN; j++) sc[tid * SCP + j] *= inv;
    }
    __syncthreads();

    for (int idx = tid; idx < WIN * HD; idx += 256) {
        int i = idx / HD;
        int d = idx % HD;
        float s = 0.f;
#pragma unroll 8
        for (int j = 0; j < WIN; j++)
            s += sc[i * SCP + j] * vs[j * HDP + d];
        size_t o = base + (size_t)i * DIM + d;
        __nv_bfloat16 hi = __float2bfloat16(s);
        g_ahi[o] = hi;
        g_alo[o] = __float2bfloat16(s - __bfloat162float(hi));
    }
}

// ---------------------------------------------------------------------------
__global__ void bias_add(float* __restrict__ out, const float* __restrict__ bp)
{
    int i = blockIdx.x * blockDim.x + threadIdx.x;
    float4 v = ((float4*)out)[i];
    int col = (i * 4) % DIM;
    v.x += bp[col + 0];
    v.y += bp[col + 1];
    v.z += bp[col + 2];
    v.w += bp[col + 3];
    ((float4*)out)[i] = v;
}

// ---------------------------------------------------------------------------
extern "C" void kernel_launch(void* const* d_in, const int* in_sizes, int n_in,
                              void* d_out, int out_size)
{
    const float* hs   = (const float*)d_in[0];
    const float* cosp = (const float*)d_in[1];
    const float* sinp = (const float*)d_in[2];
    const float* Wq   = (const float*)d_in[3];
    const float* bq   = (const float*)d_in[4];
    const float* Wk   = (const float*)d_in[5];
    const float* bk   = (const float*)d_in[6];
    const float* Wv   = (const float*)d_in[7];
    const float* bv   = (const float*)d_in[8];
    const float* Wp   = (const float*)d_in[9];
    const float* bp   = (const float*)d_in[10];
    float* out = (float*)d_out;

    float *pq, *pk, *pv;
    __nv_bfloat16 *pah, *pal, *pwh, *pwl;
    cudaGetSymbolAddress((void**)&pq,  g_q);
    cudaGetSymbolAddress((void**)&pk,  g_k);
    cudaGetSymbolAddress((void**)&pv,  g_v);
    cudaGetSymbolAddress((void**)&pah, g_ahi);
    cudaGetSymbolAddress((void**)&pal, g_alo);
    cudaGetSymbolAddress((void**)&pwh, g_whi);
    cudaGetSymbolAddress((void**)&pwl, g_wlo);

    const int nA4 = SEQ * DIM / 4;
    const int nW4 = DIM * DIM / 4;
    dim3 gg(DIM / TN, SEQ / TM);   // (5, 128)

    cudaFuncSetAttribute(gemm_tc, cudaFuncAttributeMaxDynamicSharedMemorySize, SMEM_GEMM);

    split_kernel<<<(nA4 + 255) / 256, 256>>>(hs, pah, pal, nA4);

    split_kernel<<<(nW4 + 255) / 256, 256>>>(Wq, pwh, pwl, nW4);
    gemm_tc<<<gg, 256, SMEM_GEMM>>>(pah, pal, pwh, pwl, pq);
    split_kernel<<<(nW4 + 255) / 256, 256>>>(Wk, pwh, pwl, nW4);
    gemm_tc<<<gg, 256, SMEM_GEMM>>>(pah, pal, pwh, pwl, pk);
    split_kernel<<<(nW4 + 255) / 256, 256>>>(Wv, pwh, pwl, nW4);
    gemm_tc<<<gg, 256, SMEM_GEMM>>>(pah, pal, pwh, pwl, pv);

    const int smem = (3 * WIN * HDP + WIN * SCP) * (int)sizeof(float);
    cudaFuncSetAttribute(attn_win, cudaFuncAttributeMaxDynamicSharedMemorySize, smem);
    attn_win<<<dim3(NWIN, NH), 256, smem>>>(cosp, sinp, bq, bk, bv);

    split_kernel<<<(nW4 + 255) / 256, 256>>>(Wp, pwh, pwl, nW4);
    gemm_tc<<<gg, 256, SMEM_GEMM>>>(pah, pal, pwh, pwl, out);
    bias_add<<<nA4 / 256, 256>>>(out, bp);
}

// round 6
// speedup vs baseline: 5.8981x; 1.1434x over previous
#include <cuda_runtime.h>
#include <cuda.h>
#include <cuda_bf16.h>
#include <mma.h>
#include <cstdint>

#define SEQ   16384
#define DIM   1280
#define NH    16
#define HD    80
#define WIN   64
#define NWIN  (SEQ / WIN)
#define HDP   84
#define SCP   65

// tcgen05 GEMM tiling
#define TM    128          // CTA tile M
#define TN    256          // CTA tile N (half loaded per CTA, multicast)
#define TKB   128          // K-chunk bytes per row (64 bf16) = SW128 row
#define TKE   64           // K-chunk elements
#define NSTG  (DIM / TKE)  // 20 k-stages

// smem layout (dynamic)
#define SM_TMEM   0
#define SM_FULL   8        // full[0]=8, full[1]=16
#define SM_DONE   24       // done[0]=24, done[1]=32
#define SM_BUF    1024
#define A_BYTES   (TM * TKB)                 // 16384
#define B_BYTES   (TN * TKB)                 // 32768
#define BHALF     (B_BYTES / 2)              // 16384 (one CTA's multicast slice)
#define STAGE_BYTES (2*A_BYTES + 2*B_BYTES)  // 96 KB
#define SMEM_GEMM (SM_BUF + 2 * STAGE_BYTES) // 197,632 B
#define STAGE_TX  (2*A_BYTES + 2*B_BYTES)    // 98304 bytes arrive per stage per CTA

// Arch-specific tcgen05 (TMEM ld/st) only exists on sm_10xa targets.
#if defined(__CUDA_ARCH__) && (defined(__CUDA_ARCH_FEAT_SM103_ALL) || defined(__CUDA_ARCH_FEAT_SM100_ALL))
#define TC_PATH 1
#else
#define TC_PATH 0
#endif

// ---------------------------------------------------------------------------
// Scratch
// ---------------------------------------------------------------------------
__device__ float g_q[SEQ * DIM];
__device__ float g_k[SEQ * DIM];
__device__ float g_v[SEQ * DIM];
__device__ __nv_bfloat16 g_ahi[SEQ * DIM];
__device__ __nv_bfloat16 g_alo[SEQ * DIM];
__device__ __nv_bfloat16 g_whi[3 * DIM * DIM];   // Wq|Wk|Wv stacked (Wp reuses rows 0..1279)
__device__ __nv_bfloat16 g_wlo[3 * DIM * DIM];

#if TC_PATH
// ---------------------------------------------------------------------------
// PTX helpers (sm_103a only)
// ---------------------------------------------------------------------------
__device__ __forceinline__ uint32_t smem_u32(const void* p) {
    uint32_t a;
    asm("{ .reg .u64 t; cvta.to.shared.u64 t, %1; cvt.u32.u64 %0, t; }"
        : "=r"(a) : "l"(p));
    return a;
}

__device__ __forceinline__ uint32_t ctarank() {
    uint32_t r;
    asm("mov.u32 %0, %%cluster_ctarank;" : "=r"(r));
    return r;
}

#define MBAR_INIT(addr, cnt) \
    asm volatile("mbarrier.init.shared.b64 [%0], %1;" :: "r"(addr), "r"(cnt) : "memory")

#define MBAR_EXPECT_TX(addr, tx) \
    asm volatile("mbarrier.arrive.expect_tx.shared.b64 _, [%0], %1;" :: "r"(addr), "r"(tx) : "memory")

__device__ __forceinline__ void mbar_wait(uint32_t mbar, uint32_t phase) {
    asm volatile(
        "{\n\t.reg .pred P;\n\t"
        "WL_%=:\n\t"
        "mbarrier.try_wait.parity.acquire.cta.shared::cta.b64 P, [%0], %1, 0x989680;\n\t"
        "@P bra WD_%=;\n\t"
        "bra WL_%=;\n\t"
        "WD_%=:\n\t}"
        :: "r"(mbar), "r"(phase) : "memory");
}

#define CLUSTER_SYNC() do { \
    asm volatile("barrier.cluster.arrive.aligned;" ::: "memory"); \
    asm volatile("barrier.cluster.wait.aligned;" ::: "memory"); \
} while (0)

// 2D TMA load -> own CTA smem
__device__ __forceinline__ void tma2d(uint32_t saddr, const void* tmap, int x, int y,
                                      uint32_t mbar) {
    asm volatile(
        "cp.async.bulk.tensor.2d.shared::cta.global.tile.mbarrier::complete_tx::bytes "
        "[%0], [%1, {%2, %3}], [%4];"
        :: "r"(saddr), "l"(tmap), "r"(x), "r"(y), "r"(mbar) : "memory");
}
// 2D TMA load multicast to all cluster CTAs (same smem offset)
__device__ __forceinline__ void tma2d_mc(uint32_t saddr, const void* tmap, int x, int y,
                                         uint32_t mbar, uint16_t mask) {
    asm volatile(
        "cp.async.bulk.tensor.2d.shared::cluster.global.tile.mbarrier::complete_tx::bytes"
        ".multicast::cluster [%0], [%1, {%2, %3}], [%4], %5;"
        :: "r"(saddr), "l"(tmap), "r"(x), "r"(y), "r"(mbar), "h"(mask) : "memory");
}

// SW128 K-major smem descriptor: layout=2, version=1, SBO=64, LBO=1
__device__ __forceinline__ uint64_t mk_desc(uint32_t addr) {
    return ((uint64_t)2 << 61) | ((uint64_t)1 << 46) | ((uint64_t)64 << 32) |
           ((uint64_t)1 << 16) | (uint64_t)((addr >> 4) & 0x3FFF);
}

__device__ __forceinline__ void mma_bf16_ss(uint32_t d, uint64_t ad, uint64_t bd,
                                            uint32_t idesc, uint32_t en) {
    asm volatile(
        "{\n\t.reg .pred p;\n\tsetp.ne.u32 p, %5, 0;\n\t"
        "tcgen05.mma.cta_group::1.kind::f16 [%0], %1, %2, %3, {%4, %4, %4, %4}, p;\n\t}"
        :: "r"(d), "l"(ad), "l"(bd), "r"(idesc), "r"(0u), "r"(en) : "memory");
}

// MMA-done commit, arriving at the same mbarrier offset in BOTH cluster CTAs
#define TC_COMMIT_MC(mbar, mask) \
    asm volatile("tcgen05.commit.cta_group::1.mbarrier::arrive::one.shared::cluster" \
                 ".multicast::cluster.b64 [%0], %1;" :: "r"(mbar), "h"((uint16_t)(mask)) : "memory")
#define TC_ALLOC(slot, n) \
    asm volatile("tcgen05.alloc.cta_group::1.sync.aligned.shared::cta.b32 [%0], %1;" \
                 :: "r"(slot), "r"(n) : "memory")
#define TC_RELINQ() \
    asm volatile("tcgen05.relinquish_alloc_permit.cta_group::1.sync.aligned;")
#define TC_DEALLOC(t, n) \
    asm volatile("tcgen05.dealloc.cta_group::1.sync.aligned.b32 %0, %1;" :: "r"(t), "r"(n))
#define TC_FENCE_AFTER()  asm volatile("tcgen05.fence::after_thread_sync;" ::: "memory")
#define TC_FENCE_BEFORE() asm volatile("tcgen05.fence::before_thread_sync;" ::: "memory")
#define TC_WAIT_LD() asm volatile("tcgen05.wait::ld.sync.aligned;" ::: "memory")

#define LDTM_X32(r, addr) \
    asm volatile("tcgen05.ld.sync.aligned.32x32b.x32.b32 " \
        "{%0,%1,%2,%3,%4,%5,%6,%7,%8,%9,%10,%11,%12,%13,%14,%15," \
        "%16,%17,%18,%19,%20,%21,%22,%23,%24,%25,%26,%27,%28,%29,%30,%31}, [%32];" \
        : "=r"((r)[0]),"=r"((r)[1]),"=r"((r)[2]),"=r"((r)[3]), \
          "=r"((r)[4]),"=r"((r)[5]),"=r"((r)[6]),"=r"((r)[7]), \
          "=r"((r)[8]),"=r"((r)[9]),"=r"((r)[10]),"=r"((r)[11]), \
          "=r"((r)[12]),"=r"((r)[13]),"=r"((r)[14]),"=r"((r)[15]), \
          "=r"((r)[16]),"=r"((r)[17]),"=r"((r)[18]),"=r"((r)[19]), \
          "=r"((r)[20]),"=r"((r)[21]),"=r"((r)[22]),"=r"((r)[23]), \
          "=r"((r)[24]),"=r"((r)[25]),"=r"((r)[26]),"=r"((r)[27]), \
          "=r"((r)[28]),"=r"((r)[29]),"=r"((r)[30]),"=r"((r)[31]) \
        : "r"(addr))

// idesc: fp32 accum, bf16 a/b, N=256, M=128
#define IDESC ((1u << 4) | (1u << 7) | (1u << 10) | ((TN / 8) << 17) | ((TM / 16) << 24))
#endif  // TC_PATH

// ---------------------------------------------------------------------------
// fp32 -> bf16 hi + residual lo
// ---------------------------------------------------------------------------
__global__ void split_kernel(const float* __restrict__ src,
                             __nv_bfloat16* __restrict__ hi,
                             __nv_bfloat16* __restrict__ lo, int n4)
{
    int i = blockIdx.x * blockDim.x + threadIdx.x;
    if (i >= n4) return;
    float4 v = ((const float4*)src)[i];
    __nv_bfloat16 h0 = __float2bfloat16(v.x);
    __nv_bfloat16 h1 = __float2bfloat16(v.y);
    __nv_bfloat16 h2 = __float2bfloat16(v.z);
    __nv_bfloat16 h3 = __float2bfloat16(v.w);
    __nv_bfloat16 l0 = __float2bfloat16(v.x - __bfloat162float(h0));
    __nv_bfloat16 l1 = __float2bfloat16(v.y - __bfloat162float(h1));
    __nv_bfloat16 l2 = __float2bfloat16(v.z - __bfloat162float(h2));
    __nv_bfloat16 l3 = __float2bfloat16(v.w - __bfloat162float(h3));
    __nv_bfloat162* hp = (__nv_bfloat162*)hi;
    __nv_bfloat162* lp = (__nv_bfloat162*)lo;
    hp[2 * i]     = __nv_bfloat162(h0, h1);
    hp[2 * i + 1] = __nv_bfloat162(h2, h3);
    lp[2 * i]     = __nv_bfloat162(l0, l1);
    lp[2 * i + 1] = __nv_bfloat162(l2, l3);
}

// ---------------------------------------------------------------------------
// tcgen05 bf16x3 GEMM with TMA + 2-CTA B-multicast.
// C[M,N] = (Ah+Al)[M,K] @ (Bh+Bl)[N,K]^T
// Cluster (1,2,1): pair shares bn; each CTA TMA-loads its A tile and HALF of
// the B tile (multicast to both). Buffer reuse gated by multicast MMA commits.
// fused=1: N spans Wq|Wk|Wv (grid.x=15), C -> cq/ck/cv. fused=0: C -> cq.
// ---------------------------------------------------------------------------
__global__ __launch_bounds__(256, 1) __cluster_dims__(1, 2, 1)
void gemm_tc(const __grid_constant__ CUtensorMap tmAh,
             const __grid_constant__ CUtensorMap tmAl,
             const __grid_constant__ CUtensorMap tmBh,
             const __grid_constant__ CUtensorMap tmBl,
             const __nv_bfloat16* __restrict__ Ah,
             const __nv_bfloat16* __restrict__ Al,
             const __nv_bfloat16* __restrict__ Bh,
             const __nv_bfloat16* __restrict__ Bl,
             float* cq, float* ck, float* cv, int fused)
{
    extern __shared__ char smc[];
    const int tid = threadIdx.x;
    const int wid = tid >> 5;
    const int bm = blockIdx.y * TM;
    const int bn = blockIdx.x * TN;

    // output pointer / local column
    float* C;
    int lcol;
    if (fused) {
        int mtx = blockIdx.x / 5;             // 0:q 1:k 2:v
        C = (mtx == 0) ? cq : (mtx == 1) ? ck : cv;
        lcol = (blockIdx.x % 5) * TN;
    } else {
        C = cq;
        lcol = bn;
    }

#if TC_PATH
    const int lane = tid & 31;
    const uint32_t sbase = smem_u32(smc);
    const uint32_t rank = ctarank();

    if (tid == 0) {
        MBAR_INIT(sbase + SM_FULL, 1);
        MBAR_INIT(sbase + SM_FULL + 8, 1);
        MBAR_INIT(sbase + SM_DONE, 2);        // both CTAs' commits arrive
        MBAR_INIT(sbase + SM_DONE + 8, 2);
    }
    if (wid == 0) {
        TC_ALLOC(sbase + SM_TMEM, 256);
        TC_RELINQ();
    }
    __syncthreads();
    CLUSTER_SYNC();   // barriers visible cluster-wide before any multicast TMA

    uint32_t tmem;
    asm volatile("ld.shared.b32 %0, [%1];" : "=r"(tmem) : "r"(sbase + SM_TMEM));

    if (tid == 0) {
        // stage issue: expect full tx, A local, B half multicast
        auto issue = [&](int i, int b) {
            const uint32_t buf = sbase + SM_BUF + b * STAGE_BYTES;
            const uint32_t fullb = sbase + SM_FULL + 8 * b;
            const int x = i * TKE;
            MBAR_EXPECT_TX(fullb, STAGE_TX);
            tma2d(buf,            &tmAh, x, bm, fullb);
            tma2d(buf + A_BYTES,  &tmAl, x, bm, fullb);
            const int brow = bn + (int)rank * 128;
            tma2d_mc(buf + 2 * A_BYTES + rank * BHALF,           &tmBh, x, brow, fullb, 3);
            tma2d_mc(buf + 2 * A_BYTES + B_BYTES + rank * BHALF, &tmBl, x, brow, fullb, 3);
        };

        int pfull[2] = {0, 0}, pdone[2] = {0, 0};
        issue(0, 0);
        issue(1, 1);

        for (int i = 0; i < NSTG; i++) {
            const int b = i & 1;
            mbar_wait(sbase + SM_FULL + 8 * b, pfull[b]);
            pfull[b] ^= 1;

            const uint32_t bufb = sbase + SM_BUF + b * STAGE_BYTES;
            uint64_t adh = mk_desc(bufb);
            uint64_t adl = mk_desc(bufb + A_BYTES);
            uint64_t bdh = mk_desc(bufb + 2 * A_BYTES);
            uint64_t bdl = mk_desc(bufb + 2 * A_BYTES + B_BYTES);
#pragma unroll
            for (int ks = 0; ks < 4; ks++) {
                mma_bf16_ss(tmem, adh + 2 * ks, bdh + 2 * ks, IDESC,
                            (i == 0 && ks == 0) ? 0u : 1u);
                mma_bf16_ss(tmem, adh + 2 * ks, bdl + 2 * ks, IDESC, 1u);
                mma_bf16_ss(tmem, adl + 2 * ks, bdh + 2 * ks, IDESC, 1u);
            }
            TC_COMMIT_MC(sbase + SM_DONE + 8 * b, 3);

            if (i + 2 < NSTG) {
                // both CTAs' MMAs on buffer b must retire before refill
                mbar_wait(sbase + SM_DONE + 8 * b, pdone[b]);
                pdone[b] ^= 1;
                issue(i + 2, b);
            }
        }
        // final stage (NSTG-1, buffer 1) fully retired on both CTAs
        mbar_wait(sbase + SM_DONE + 8 * ((NSTG - 1) & 1), pdone[(NSTG - 1) & 1]);
    }

    __syncthreads();
    TC_FENCE_AFTER();

    // epilogue: warps 0-3 each read their 32-row TMEM subpartition
    if (wid < 4) {
        float* crow = C + (size_t)(bm + wid * 32 + lane) * DIM + lcol;
#pragma unroll
        for (int cc = 0; cc < 8; cc++) {
            uint32_t r[32];
            LDTM_X32(r, tmem + cc * 32);
            TC_WAIT_LD();
            uint4* cp = (uint4*)(crow + cc * 32);
#pragma unroll
            for (int q = 0; q < 8; q++)
                cp[q] = make_uint4(r[4 * q], r[4 * q + 1], r[4 * q + 2], r[4 * q + 3]);
        }
        TC_FENCE_BEFORE();
    }

    __syncthreads();
    if (wid == 0) TC_DEALLOC(tmem, 256);
    CLUSTER_SYNC();   // no CTA exits while peer multicasts could target its smem

#else  // ------- wmma fallback (family/generic targets; correctness net) -----
    using namespace nvcuda;
    const int GLDS = 40;
    __nv_bfloat16* sAh = (__nv_bfloat16*)smc;
    __nv_bfloat16* sAl = sAh + 128 * GLDS;
    __nv_bfloat16* sBh = sAl + 128 * GLDS;
    __nv_bfloat16* sBl = sBh + 128 * GLDS;

    const int wm = (wid & 1) * 64;
    const int wn = (wid >> 1) * 32;
    const int r0 = tid >> 2;
    const int c0 = (tid & 3) * 8;

    for (int half = 0; half < 2; half++) {
        const int bnh = bn + half * 128;
        wmma::fragment<wmma::accumulator, 16, 16, 16, float> acc[4][2];
#pragma unroll
        for (int i = 0; i < 4; i++)
#pragma unroll
            for (int j = 0; j < 2; j++) wmma::fill_fragment(acc[i][j], 0.0f);

        for (int k0 = 0; k0 < DIM; k0 += 32) {
            __syncthreads();
#pragma unroll
            for (int rr = 0; rr < 2; rr++) {
                int row = r0 + rr * 64;
                size_t ga = (size_t)(bm + row) * DIM + k0 + c0;
                size_t gb = (size_t)(bnh + row) * DIM + k0 + c0;
                *(uint4*)&sAh[row * GLDS + c0] = *(const uint4*)(Ah + ga);
                *(uint4*)&sAl[row * GLDS + c0] = *(const uint4*)(Al + ga);
                *(uint4*)&sBh[row * GLDS + c0] = *(const uint4*)(Bh + gb);
                *(uint4*)&sBl[row * GLDS + c0] = *(const uint4*)(Bl + gb);
            }
            __syncthreads();
#pragma unroll
            for (int kk = 0; kk < 32; kk += 16) {
                wmma::fragment<wmma::matrix_a, 16, 16, 16, __nv_bfloat16, wmma::row_major> fah[4], fal[4];
                wmma::fragment<wmma::matrix_b, 16, 16, 16, __nv_bfloat16, wmma::col_major> fbh[2], fbl[2];
#pragma unroll
                for (int i = 0; i < 4; i++) {
                    wmma::load_matrix_sync(fah[i], &sAh[(wm + i * 16) * GLDS + kk], GLDS);
                    wmma::load_matrix_sync(fal[i], &sAl[(wm + i * 16) * GLDS + kk], GLDS);
                }
#pragma unroll
                for (int j = 0; j < 2; j++) {
                    wmma::load_matrix_sync(fbh[j], &sBh[(wn + j * 16) * GLDS + kk], GLDS);
                    wmma::load_matrix_sync(fbl[j], &sBl[(wn + j * 16) * GLDS + kk], GLDS);
                }
#pragma unroll
                for (int i = 0; i < 4; i++)
#pragma unroll
                    for (int j = 0; j < 2; j++) {
                        wmma::mma_sync(acc[i][j], fah[i], fbh[j], acc[i][j]);
                        wmma::mma_sync(acc[i][j], fah[i], fbl[j], acc[i][j]);
                        wmma::mma_sync(acc[i][j], fal[i], fbh[j], acc[i][j]);
                    }
            }
        }
#pragma unroll
        for (int i = 0; i < 4; i++)
#pragma unroll
            for (int j = 0; j < 2; j++)
                wmma::store_matrix_sync(&C[(size_t)(bm + wm + i * 16) * DIM + lcol + half * 128 + wn + j * 16],
                                        acc[i][j], DIM, wmma::mem_row_major);
        __syncthreads();
    }
#endif
}

// ---------------------------------------------------------------------------
// Windowed attention, fused bias + RoPE; writes bf16 hi/lo split
// ---------------------------------------------------------------------------
__global__ __launch_bounds__(256)
void attn_win(const float* __restrict__ cosp, const float* __restrict__ sinp,
              const float* __restrict__ bq, const float* __restrict__ bk,
              const float* __restrict__ bv)
{
    extern __shared__ float sm[];
    float* qs = sm;
    float* ks = qs + WIN * HDP;
    float* vs = ks + WIN * HDP;
    float* sc = vs + WIN * HDP;

    const int w = blockIdx.x;
    const int h = blockIdx.y;
    const int tid = threadIdx.x;
    const size_t base = (size_t)(w * WIN) * DIM + (size_t)h * HD;

    for (int idx = tid; idx < WIN * (HD / 2); idx += 256) {
        int row = idx / (HD / 2);
        int d   = idx % (HD / 2);
        int s   = w * WIN + row;
        float c1 = cosp[s * HD + d],          s1 = sinp[s * HD + d];
        float c2 = cosp[s * HD + d + HD / 2], s2 = sinp[s * HD + d + HD / 2];
        size_t o1 = base + (size_t)row * DIM + d;
        size_t o2 = o1 + HD / 2;

        float q1 = g_q[o1] + bq[h * HD + d];
        float q2 = g_q[o2] + bq[h * HD + d + HD / 2];
        qs[row * HDP + d]          = q1 * c1 - q2 * s1;
        qs[row * HDP + d + HD / 2] = q2 * c2 + q1 * s2;

        float k1 = g_k[o1] + bk[h * HD + d];
        float k2 = g_k[o2] + bk[h * HD + d + HD / 2];
        ks[row * HDP + d]          = k1 * c1 - k2 * s1;
        ks[row * HDP + d + HD / 2] = k2 * c2 + k1 * s2;
    }
    for (int idx = tid; idx < WIN * (HD / 4); idx += 256) {
        int row = idx / (HD / 4);
        int col = (idx % (HD / 4)) * 4;
        size_t g = base + (size_t)row * DIM + col;
        float4 vv = *(const float4*)(g_v + g);
        vv.x += bv[h * HD + col + 0];
        vv.y += bv[h * HD + col + 1];
        vv.z += bv[h * HD + col + 2];
        vv.w += bv[h * HD + col + 3];
        *(float4*)(vs + row * HDP + col) = vv;
    }
    __syncthreads();

    const float scale = 0.11180339887498949f;
    {
        const int i  = tid & 63;
        const int jb = (tid >> 6) * 16;
        for (int j = jb; j < jb + 16; j++) {
            float s = 0.f;
#pragma unroll
            for (int d = 0; d < HD; d += 4) {
                float4 qv = *(const float4*)(qs + i * HDP + d);
                float4 kv = *(const float4*)(ks + j * HDP + d);
                s += qv.x * kv.x + qv.y * kv.y + qv.z * kv.z + qv.w * kv.w;
            }
            sc[i * SCP + j] = s * scale;
        }
    }
    __syncthreads();

    if (tid < WIN) {
        float m = -1e30f;
        for (int j = 0; j < WIN; j++) m = fmaxf(m, sc[tid * SCP + j]);
        float sum = 0.f;
        for (int j = 0; j < WIN; j++) {
            float e = __expf(sc[tid * SCP + j] - m);
            sc[tid * SCP + j] = e;
            sum += e;
        }
        float inv = 1.f / sum;
        for (int j = 0; j < WIN; j++) sc[tid * SCP + j] *= inv;
    }
    __syncthreads();

    for (int idx = tid; idx < WIN * HD; idx += 256) {
        int i = idx / HD;
        int d = idx % HD;
        float s = 0.f;
#pragma unroll 8
        for (int j = 0; j < WIN; j++)
            s += sc[i * SCP + j] * vs[j * HDP + d];
        size_t o = base + (size_t)i * DIM + d;
        __nv_bfloat16 hi = __float2bfloat16(s);
        g_ahi[o] = hi;
        g_alo[o] = __float2bfloat16(s - __bfloat162float(hi));
    }
}

// ---------------------------------------------------------------------------
__global__ void bias_add(float* __restrict__ out, const float* __restrict__ bp)
{
    int i = blockIdx.x * blockDim.x + threadIdx.x;
    float4 v = ((float4*)out)[i];
    int col = (i * 4) % DIM;
    v.x += bp[col + 0];
    v.y += bp[col + 1];
    v.z += bp[col + 2];
    v.w += bp[col + 3];
    ((float4*)out)[i] = v;
}

// ---------------------------------------------------------------------------
typedef CUresult (*PFN_tmap_encode)(
    CUtensorMap*, CUtensorMapDataType, cuuint32_t, void*,
    const cuuint64_t*, const cuuint64_t*, const cuuint32_t*, const cuuint32_t*,
    CUtensorMapInterleave, CUtensorMapSwizzle, CUtensorMapL2promotion,
    CUtensorMapFloatOOBfill);

static void encode_map(PFN_tmap_encode enc, CUtensorMap* m, void* base, uint64_t rows)
{
    cuuint64_t dims[2]    = {DIM, rows};
    cuuint64_t strides[1] = {DIM * 2};           // bytes
    cuuint32_t box[2]     = {64, 128};           // 128B x 128 rows (SW128 atom)
    cuuint32_t es[2]      = {1, 1};
    enc(m, CU_TENSOR_MAP_DATA_TYPE_BFLOAT16, 2, base, dims, strides, box, es,
        CU_TENSOR_MAP_INTERLEAVE_NONE, CU_TENSOR_MAP_SWIZZLE_128B,
        CU_TENSOR_MAP_L2_PROMOTION_L2_128B, CU_TENSOR_MAP_FLOAT_OOB_FILL_NONE);
}

extern "C" void kernel_launch(void* const* d_in, const int* in_sizes, int n_in,
                              void* d_out, int out_size)
{
    const float* hs   = (const float*)d_in[0];
    const float* cosp = (const float*)d_in[1];
    const float* sinp = (const float*)d_in[2];
    const float* Wq   = (const float*)d_in[3];
    const float* bq   = (const float*)d_in[4];
    const float* Wk   = (const float*)d_in[5];
    const float* bk   = (const float*)d_in[6];
    const float* Wv   = (const float*)d_in[7];
    const float* bv   = (const float*)d_in[8];
    const float* Wp   = (const float*)d_in[9];
    const float* bp   = (const float*)d_in[10];
    float* out = (float*)d_out;

    float *pq, *pk, *pv;
    __nv_bfloat16 *pah, *pal, *pwh, *pwl;
    cudaGetSymbolAddress((void**)&pq,  g_q);
    cudaGetSymbolAddress((void**)&pk,  g_k);
    cudaGetSymbolAddress((void**)&pv,  g_v);
    cudaGetSymbolAddress((void**)&pah, g_ahi);
    cudaGetSymbolAddress((void**)&pal, g_alo);
    cudaGetSymbolAddress((void**)&pwh, g_whi);
    cudaGetSymbolAddress((void**)&pwl, g_wlo);

    // tensormaps (driver entry point via runtime; no -lcuda link dependency)
    PFN_tmap_encode enc = nullptr;
    cudaDriverEntryPointQueryResult qr;
    cudaGetDriverEntryPoint("cuTensorMapEncodeTiled", (void**)&enc,
                            cudaEnableDefault, &qr);
    CUtensorMap tmAh, tmAl, tmBh, tmBl;
    encode_map(enc, &tmAh, pah, SEQ);
    encode_map(enc, &tmAl, pal, SEQ);
    encode_map(enc, &tmBh, pwh, 3 * DIM);
    encode_map(enc, &tmBl, pwl, 3 * DIM);

    const int nA4 = SEQ * DIM / 4;
    const int nW4 = DIM * DIM / 4;

    cudaFuncSetAttribute(gemm_tc, cudaFuncAttributeMaxDynamicSharedMemorySize, SMEM_GEMM);

    // splits: activations once; Wq|Wk|Wv stacked
    split_kernel<<<(nA4 + 255) / 256, 256>>>(hs, pah, pal, nA4);
    split_kernel<<<(nW4 + 255) / 256, 256>>>(Wq, pwh,                pwl,                nW4);
    split_kernel<<<(nW4 + 255) / 256, 256>>>(Wk, pwh + DIM * DIM,     pwl + DIM * DIM,     nW4);
    split_kernel<<<(nW4 + 255) / 256, 256>>>(Wv, pwh + 2 * DIM * DIM, pwl + 2 * DIM * DIM, nW4);

    // fused QKV GEMM: grid (15, 128), cluster (1,2,1)
    gemm_tc<<<dim3(3 * DIM / TN, SEQ / TM), 256, SMEM_GEMM>>>(
        tmAh, tmAl, tmBh, tmBl, pah, pal, pwh, pwl, pq, pk, pv, 1);

    // attention (fused bias + rope) -> bf16 split into g_ahi/g_alo
    const int smem = (3 * WIN * HDP + WIN * SCP) * (int)sizeof(float);
    cudaFuncSetAttribute(attn_win, cudaFuncAttributeMaxDynamicSharedMemorySize, smem);
    attn_win<<<dim3(NWIN, NH), 256, smem>>>(cosp, sinp, bq, bk, bv);

    // output projection: Wp into weight rows 0..1279, then GEMM grid (5, 128)
    split_kernel<<<(nW4 + 255) / 256, 256>>>(Wp, pwh, pwl, nW4);
    gemm_tc<<<dim3(DIM / TN, SEQ / TM), 256, SMEM_GEMM>>>(
        tmAh, tmAl, tmBh, tmBl, pah, pal, pwh, pwl, out, out, out, 0);
    bias_add<<<nA4 / 256, 256>>>(out, bp);
}